// round 10
// baseline (speedup 1.0000x reference)
#include <cuda_runtime.h>
#include <cuda_fp16.h>
#include <cstdint>
#include <cfloat>

// VectorQuantizer: x [N,256] fp32, emb [K,256] fp32.
// Out (fp32): quantized [N*256] | loss [1] | indices [N].
// fp16 mma (f16 accum) prefilter, margin 3e-3, K-split-2 grid (wave fix),
// exact fp32-chain rescore (bit-exact) + epilogue.

#define DIM   256
#define NMAX  65536
#define KMAX  4096
#define CAP   128
#define MG    3e-3f
#define BM    64
#define BN    64
#define KSPL  2

__device__ __align__(16) float  g_S[NMAX];
__device__ __align__(16) float  g_c[KMAX];
__device__ int            g_rm[NMAX];          // global running min (float bits)
__device__ int            g_idx[NMAX];
__device__ unsigned int   g_cnt[NMAX];
__device__ unsigned long long g_cand[(size_t)NMAX * CAP];
__device__ __align__(16) __half g_xh[(size_t)NMAX * DIM];
__device__ __align__(16) __half g_eh[(size_t)KMAX * DIM];
__device__ double         g_acc;

// ---------------------------------------------------------------------------
__global__ __launch_bounds__(256) void k_prep_x(const float* __restrict__ x, int N) {
    int n = blockIdx.x * blockDim.x + threadIdx.x;
    if (n >= N) return;
    g_cnt[n] = 0u;
    g_rm[n]  = 0x7f7fffff;
    const float4* xr = (const float4*)(x + (size_t)n * DIM);
    __half2* dst = (__half2*)(g_xh + (size_t)n * DIM);
    float s = 0.0f;
    #pragma unroll 8
    for (int i = 0; i < 64; i++) {
        float4 v = __ldg(xr + i);
        s = __fadd_rn(s, __fmul_rn(v.x, v.x));
        s = __fadd_rn(s, __fmul_rn(v.y, v.y));
        s = __fadd_rn(s, __fmul_rn(v.z, v.z));
        s = __fadd_rn(s, __fmul_rn(v.w, v.w));
        dst[2 * i + 0] = __floats2half2_rn(v.x, v.y);
        dst[2 * i + 1] = __floats2half2_rn(v.z, v.w);
    }
    g_S[n] = s;
}

__global__ __launch_bounds__(256) void k_prep_e(const float* __restrict__ emb, int K) {
    int k = blockIdx.x * blockDim.x + threadIdx.x;
    if (k == 0) g_acc = 0.0;
    if (k >= K) return;
    const float4* er = (const float4*)(emb + (size_t)k * DIM);
    __half2* dst = (__half2*)(g_eh + (size_t)k * DIM);
    float s = 0.0f;
    #pragma unroll 8
    for (int i = 0; i < 64; i++) {
        float4 v = __ldg(er + i);
        s = __fadd_rn(s, __fmul_rn(v.x, v.x));
        s = __fadd_rn(s, __fmul_rn(v.y, v.y));
        s = __fadd_rn(s, __fmul_rn(v.z, v.z));
        s = __fadd_rn(s, __fmul_rn(v.w, v.w));
        dst[2 * i + 0] = __floats2half2_rn(v.x, v.y);
        dst[2 * i + 1] = __floats2half2_rn(v.z, v.w);
    }
    g_c[k] = s;
}

// ---------------------------------------------------------------------------
__device__ __forceinline__ void cpa16(uint32_t s, const void* g) {
    asm volatile("cp.async.cg.shared.global [%0], [%1], 16;\n" :: "r"(s), "l"(g));
}
__device__ __forceinline__ void ldsm4(uint32_t* r, uint32_t a) {
    asm volatile("ldmatrix.sync.aligned.m8n8.x4.shared.b16 {%0,%1,%2,%3}, [%4];"
        : "=r"(r[0]), "=r"(r[1]), "=r"(r[2]), "=r"(r[3]) : "r"(a));
}
// f16 accum: D = {d0,d1} packed half2 (d0 rows g, d1 rows g+8; cols 2t,2t+1)
__device__ __forceinline__ void mma16816h(uint32_t* d, const uint32_t* a,
                                          uint32_t b0, uint32_t b1) {
    asm volatile("mma.sync.aligned.m16n8k16.row.col.f16.f16.f16.f16 "
        "{%0,%1}, {%2,%3,%4,%5}, {%6,%7}, {%0,%1};"
        : "+r"(d[0]), "+r"(d[1])
        : "r"(a[0]), "r"(a[1]), "r"(a[2]), "r"(a[3]), "r"(b0), "r"(b1));
}

// fp16 tile: row r = 512B (256 dims), 32 units of 16B, low-3-bit XOR swizzle
__device__ __forceinline__ uint32_t xoff(int r, int j) {
    return (uint32_t)((r << 9) + (((j & 24) | ((j ^ r) & 7)) << 4));
}

// smem map (bytes)
#define SM_XS  0                       // 64*512 = 32768
#define SM_ES  32768                   // 2 * 32768
#define SM_SC  (SM_ES + 2 * 32768)     // 2 * 256B c chunks
#define SM_SS  (SM_SC + 512)           // 64 * 4
#define SM_RM  (SM_SS + 256)           // 64 * 4
#define SM_TOT (SM_RM + 256)

__global__ __launch_bounds__(256, 2) void k_gemm(int N, int K) {
    extern __shared__ char smem[];
    const uint32_t sb = (uint32_t)__cvta_generic_to_shared(smem);
    float* sS  = (float*)(smem + SM_SS);
    int*   srm = (int*)  (smem + SM_RM);

    const int tid  = threadIdx.x;
    const int lane = tid & 31, wid = tid >> 5;
    const int rb   = (blockIdx.x >> 1) * BM;          // row tile
    const int koff = (blockIdx.x & 1) * (K / KSPL);   // code half
    const int nch  = K / KSPL / BN;                   // 32 chunks

    if (tid < BM) { srm[tid] = 0x7f7fffff; sS[tid] = g_S[rb + tid]; }

    for (int i = tid; i < BM * 32; i += 256) {
        int r = i >> 5, j = i & 31;
        cpa16(sb + SM_XS + xoff(r, j), g_xh + (size_t)(rb + r) * DIM + j * 8);
        cpa16(sb + SM_ES + xoff(r, j), g_eh + (size_t)(koff + r) * DIM + j * 8);
    }
    if (tid < 16) cpa16(sb + SM_SC + tid * 16, g_c + koff + tid * 4);
    asm volatile("cp.async.commit_group;\n");

    const int mi = wid >> 2;       // 0..1 : 32-row group
    const int ni = wid & 3;        // 0..3 : 16-col group
    const int g  = lane >> 2, t = lane & 3;

    for (int ci = 0; ci < nch; ci++) {
        const int buf = ci & 1;
        asm volatile("cp.async.wait_group 0;\n");
        __syncthreads();

        if (ci + 1 < nch) {
            const int nb = (ci + 1) & 1;
            for (int i = tid; i < BN * 32; i += 256) {
                int r = i >> 5, j = i & 31;
                cpa16(sb + SM_ES + nb * 32768 + xoff(r, j),
                      g_eh + (size_t)(koff + (ci + 1) * BN + r) * DIM + j * 8);
            }
            if (tid < 16) cpa16(sb + SM_SC + nb * 256 + tid * 16,
                                g_c + koff + (ci + 1) * BN + tid * 4);
            asm volatile("cp.async.commit_group;\n");
        }

        uint32_t acc[2][2][2];         // [mt][nf][half2: rows g / g+8]
        #pragma unroll
        for (int mt = 0; mt < 2; mt++)
            #pragma unroll
            for (int nf = 0; nf < 2; nf++) { acc[mt][nf][0] = 0u; acc[mt][nf][1] = 0u; }

        const uint32_t esb = sb + SM_ES + buf * 32768;
        #pragma unroll
        for (int ks = 0; ks < 16; ks++) {
            uint32_t a[2][4], b[4];
            #pragma unroll
            for (int mt = 0; mt < 2; mt++) {
                int r = mi * 32 + mt * 16 + (lane & 7) + ((lane >> 3) & 1) * 8;
                ldsm4(a[mt], sb + SM_XS + xoff(r, ks * 2 + (lane >> 4)));
            }
            {
                int r = ni * 16 + (lane & 7) + (lane >> 4) * 8;
                ldsm4(b, esb + xoff(r, ks * 2 + ((lane >> 3) & 1)));
            }
            #pragma unroll
            for (int mt = 0; mt < 2; mt++) {
                mma16816h(acc[mt][0], a[mt], b[0], b[1]);
                mma16816h(acc[mt][1], a[mt], b[2], b[3]);
            }
        }

        // distances: unpack f16 accum, d~ = fadd(fma(-2,M,S), c)
        const float* scb = (const float*)(smem + SM_SC + buf * 256);
        float dist[2][2][2][2];        // [mt][h][nf][q]
        #pragma unroll
        for (int mt = 0; mt < 2; mt++)
            #pragma unroll
            for (int nf = 0; nf < 2; nf++)
                #pragma unroll
                for (int h = 0; h < 2; h++) {
                    __half2 hv = *reinterpret_cast<__half2*>(&acc[mt][nf][h]);
                    float2 fv = __half22float2(hv);
                    const int rl = mi * 32 + mt * 16 + g + h * 8;
                    const int cl = ni * 16 + nf * 8 + 2 * t;
                    dist[mt][h][nf][0] = __fadd_rn(
                        __fmaf_rn(-2.0f, fv.x, sS[rl]), scb[cl]);
                    dist[mt][h][nf][1] = __fadd_rn(
                        __fmaf_rn(-2.0f, fv.y, sS[rl]), scb[cl + 1]);
                }

        if (ci == 0) {
            #pragma unroll
            for (int mt = 0; mt < 2; mt++)
                #pragma unroll
                for (int h = 0; h < 2; h++) {
                    const int rl = mi * 32 + mt * 16 + g + h * 8;
                    float lmin = fminf(fminf(dist[mt][h][0][0], dist[mt][h][0][1]),
                                       fminf(dist[mt][h][1][0], dist[mt][h][1][1]));
                    lmin = fminf(lmin, __shfl_xor_sync(0xffffffffu, lmin, 1));
                    lmin = fminf(lmin, __shfl_xor_sync(0xffffffffu, lmin, 2));
                    if (t == 0) atomicMin(&srm[rl], __float_as_int(lmin));
                }
            __syncthreads();
        }
        const int cb = koff + ci * BN + ni * 16;
        #pragma unroll
        for (int mt = 0; mt < 2; mt++)
            #pragma unroll
            for (int h = 0; h < 2; h++) {
                const int rl = mi * 32 + mt * 16 + g + h * 8;
                const float rmw = __int_as_float(srm[rl]) + MG;
                float lmin = FLT_MAX;
                #pragma unroll
                for (int nf = 0; nf < 2; nf++)
                    #pragma unroll
                    for (int q = 0; q < 2; q++) {
                        float d = dist[mt][h][nf][q];
                        lmin = fminf(lmin, d);
                        if (d <= rmw) {
                            unsigned int pos = atomicAdd(&g_cnt[rb + rl], 1u);
                            if (pos < CAP)
                                g_cand[(size_t)(rb + rl) * CAP + pos] =
                                    ((unsigned long long)__float_as_uint(d) << 32)
                                    | (unsigned int)(cb + nf * 8 + 2 * t + q);
                        }
                    }
                if (ci > 0) {
                    lmin = fminf(lmin, __shfl_xor_sync(0xffffffffu, lmin, 1));
                    lmin = fminf(lmin, __shfl_xor_sync(0xffffffffu, lmin, 2));
                    if (t == 0) atomicMin(&srm[rl], __float_as_int(lmin));
                }
            }
    }
    __syncthreads();
    if (tid < BM) atomicMin(&g_rm[rb + tid], srm[tid]);
}

// ---------------------------------------------------------------------------
__device__ __forceinline__ unsigned long long exact_pack(
        const float* xr, const float* emb, float Sv, unsigned int k) {
    const float* er = emb + (size_t)k * DIM;
    float m = 0.0f;
    #pragma unroll 4
    for (int i = 0; i < 64; i++) {
        float4 xv = __ldg((const float4*)xr + i);
        float4 ev = __ldg((const float4*)er + i);
        m = __fmaf_rn(xv.x, ev.x, m);
        m = __fmaf_rn(xv.y, ev.y, m);
        m = __fmaf_rn(xv.z, ev.z, m);
        m = __fmaf_rn(xv.w, ev.w, m);
    }
    float d = __fadd_rn(__fmaf_rn(-2.0f, m, Sv), g_c[k]);
    return ((unsigned long long)__float_as_uint(d) << 32) | k;
}

__global__ __launch_bounds__(256) void k_rescore(const float* __restrict__ x,
                                                 const float* __restrict__ emb,
                                                 int N, int K) {
    const int w = (blockIdx.x * blockDim.x + threadIdx.x) >> 5;
    const int lane = threadIdx.x & 31;
    if (w >= N) return;
    const unsigned int cnt = g_cnt[w];
    const float Sv  = g_S[w];
    const float* xr = x + (size_t)w * DIM;
    unsigned long long best = 0xffffffffffffffffULL;
    if (cnt <= CAP) {
        const float thr = __int_as_float(g_rm[w]) + MG;
        for (unsigned int e = lane; e < cnt; e += 32) {
            unsigned long long ent = g_cand[(size_t)w * CAP + e];
            float dt = __uint_as_float((unsigned int)(ent >> 32));
            if (dt > thr) continue;
            unsigned long long v =
                exact_pack(xr, emb, Sv, (unsigned int)(ent & 0xffffffffu));
            if (v < best) best = v;
        }
    } else {
        for (int k = lane; k < K; k += 32) {
            unsigned long long v = exact_pack(xr, emb, Sv, (unsigned int)k);
            if (v < best) best = v;
        }
    }
    #pragma unroll
    for (int o = 16; o; o >>= 1) {
        unsigned long long v = __shfl_xor_sync(0xffffffffu, best, o);
        if (v < best) best = v;
    }
    if (lane == 0) g_idx[w] = (int)(best & 0xffffffffu);
}

// ---------------------------------------------------------------------------
__global__ __launch_bounds__(256) void k_epi(const float* __restrict__ x,
                                             const float* __restrict__ emb,
                                             float* __restrict__ out,
                                             float* __restrict__ outIdx, int N) {
    __shared__ double red[256];
    const int nvec = N * (DIM / 4);
    const int stride = gridDim.x * blockDim.x;
    double ls = 0.0;
    for (int tno = blockIdx.x * blockDim.x + threadIdx.x; tno < nvec; tno += stride) {
        const int n   = tno >> 6;
        const int idx = g_idx[n];
        const float4 xv = reinterpret_cast<const float4*>(x)[tno];
        const float4 ev = reinterpret_cast<const float4*>(emb)
                              [(size_t)idx * (DIM / 4) + (tno & 63)];
        float d0 = __fsub_rn(ev.x, xv.x), d1 = __fsub_rn(ev.y, xv.y);
        float d2 = __fsub_rn(ev.z, xv.z), d3 = __fsub_rn(ev.w, xv.w);
        float4 o;
        o.x = __fadd_rn(xv.x, d0); o.y = __fadd_rn(xv.y, d1);
        o.z = __fadd_rn(xv.z, d2); o.w = __fadd_rn(xv.w, d3);
        reinterpret_cast<float4*>(out)[tno] = o;
        ls += (double)__fmul_rn(d0, d0) + (double)__fmul_rn(d1, d1)
            + (double)__fmul_rn(d2, d2) + (double)__fmul_rn(d3, d3);
        if (outIdx != nullptr && (tno & 63) == 0) outIdx[n] = (float)idx;
    }
    red[threadIdx.x] = ls;
    __syncthreads();
    #pragma unroll
    for (int s = 128; s > 0; s >>= 1) {
        if (threadIdx.x < s) red[threadIdx.x] += red[threadIdx.x + s];
        __syncthreads();
    }
    if (threadIdx.x == 0) atomicAdd(&g_acc, red[0]);
}

__global__ void k_fin(float* __restrict__ out, int N) {
    double m = g_acc / ((double)N * (double)DIM);
    float L = (float)m;
    out[(size_t)N * DIM] = __fadd_rn(L, __fmul_rn(0.25f, L));
}

// ---------------------------------------------------------------------------
extern "C" void kernel_launch(void* const* d_in, const int* in_sizes, int n_in,
                              void* d_out, int out_size) {
    const float* x   = (const float*)d_in[0];
    const float* emb = (const float*)d_in[1];
    const int N = in_sizes[0] / DIM;
    const int K = in_sizes[1] / DIM;
    float* out = (float*)d_out;

    const long long Nq = (long long)N * DIM;
    const bool has_loss = (long long)out_size > Nq;
    const bool has_idx  = (long long)out_size >= Nq + 1 + N;
    float* outIdx = has_idx ? out + Nq + 1 : nullptr;

    cudaFuncSetAttribute(k_gemm, cudaFuncAttributeMaxDynamicSharedMemorySize,
                         SM_TOT);

    k_prep_e<<<(K + 255) / 256, 256>>>(emb, K);
    k_prep_x<<<(N + 255) / 256, 256>>>(x, N);
    k_gemm<<<(N / BM) * KSPL, 256, SM_TOT>>>(N, K);
    k_rescore<<<(N * 32 + 255) / 256, 256>>>(x, emb, N, K);
    k_epi<<<1184, 256>>>(x, emb, out, outIdx, N);
    if (has_loss) k_fin<<<1, 1>>>(out, N);
}

// round 11
// speedup vs baseline: 1.7646x; 1.7646x over previous
#include <cuda_runtime.h>
#include <cuda_bf16.h>
#include <cstdint>
#include <cfloat>

// VectorQuantizer: x [N,256] fp32, emb [K,256] fp32.
// Out (fp32): quantized [N*256] | loss [1] | indices [N].
// R11 = R8 (bf16 f32-accum mma prefilter + fused exact tail) + K-split 2
// with last-block-done tail to fix wave quantization (3.46 -> 6.92 waves).

#define DIM   256
#define NMAX  65536
#define KMAX  4096
#define CAP   128
#define MG    2e-3f
#define BM    64
#define BN    64
#define KSPL  2

__device__ __align__(16) float  g_S[NMAX];
__device__ __align__(16) float  g_c[KMAX];
__device__ int            g_rm[NMAX];           // global running min (float bits)
__device__ unsigned int   g_cnt[NMAX];
__device__ unsigned int   g_done[NMAX / BM];
__device__ unsigned long long g_cand[(size_t)NMAX * CAP];
__device__ __align__(16) __nv_bfloat16 g_xb[(size_t)NMAX * DIM];
__device__ __align__(16) __nv_bfloat16 g_eb[(size_t)KMAX * DIM];
__device__ double         g_acc;

// ---------------------------------------------------------------------------
__global__ __launch_bounds__(256) void k_prep_x(const float* __restrict__ x, int N) {
    int n = blockIdx.x * blockDim.x + threadIdx.x;
    if (n >= N) return;
    g_cnt[n] = 0u;
    g_rm[n]  = 0x7f7fffff;
    if (n < N / BM) g_done[n] = 0u;
    const float4* xr = (const float4*)(x + (size_t)n * DIM);
    __nv_bfloat162* dst = (__nv_bfloat162*)(g_xb + (size_t)n * DIM);
    float s = 0.0f;
    #pragma unroll 8
    for (int i = 0; i < 64; i++) {
        float4 v = __ldg(xr + i);
        s = __fadd_rn(s, __fmul_rn(v.x, v.x));
        s = __fadd_rn(s, __fmul_rn(v.y, v.y));
        s = __fadd_rn(s, __fmul_rn(v.z, v.z));
        s = __fadd_rn(s, __fmul_rn(v.w, v.w));
        dst[2 * i + 0] = __floats2bfloat162_rn(v.x, v.y);
        dst[2 * i + 1] = __floats2bfloat162_rn(v.z, v.w);
    }
    g_S[n] = s;
}

__global__ __launch_bounds__(256) void k_prep_e(const float* __restrict__ emb, int K) {
    int k = blockIdx.x * blockDim.x + threadIdx.x;
    if (k == 0) g_acc = 0.0;
    if (k >= K) return;
    const float4* er = (const float4*)(emb + (size_t)k * DIM);
    __nv_bfloat162* dst = (__nv_bfloat162*)(g_eb + (size_t)k * DIM);
    float s = 0.0f;
    #pragma unroll 8
    for (int i = 0; i < 64; i++) {
        float4 v = __ldg(er + i);
        s = __fadd_rn(s, __fmul_rn(v.x, v.x));
        s = __fadd_rn(s, __fmul_rn(v.y, v.y));
        s = __fadd_rn(s, __fmul_rn(v.z, v.z));
        s = __fadd_rn(s, __fmul_rn(v.w, v.w));
        dst[2 * i + 0] = __floats2bfloat162_rn(v.x, v.y);
        dst[2 * i + 1] = __floats2bfloat162_rn(v.z, v.w);
    }
    g_c[k] = s;
}

// ---------------------------------------------------------------------------
__device__ __forceinline__ void cpa16(uint32_t s, const void* g) {
    asm volatile("cp.async.cg.shared.global [%0], [%1], 16;\n" :: "r"(s), "l"(g));
}
__device__ __forceinline__ void ldsm4(uint32_t* r, uint32_t a) {
    asm volatile("ldmatrix.sync.aligned.m8n8.x4.shared.b16 {%0,%1,%2,%3}, [%4];"
        : "=r"(r[0]), "=r"(r[1]), "=r"(r[2]), "=r"(r[3]) : "r"(a));
}
__device__ __forceinline__ void mma16816(float* d, const uint32_t* a,
                                         uint32_t b0, uint32_t b1) {
    asm volatile("mma.sync.aligned.m16n8k16.row.col.f32.bf16.bf16.f32 "
        "{%0,%1,%2,%3}, {%4,%5,%6,%7}, {%8,%9}, {%0,%1,%2,%3};"
        : "+f"(d[0]), "+f"(d[1]), "+f"(d[2]), "+f"(d[3])
        : "r"(a[0]), "r"(a[1]), "r"(a[2]), "r"(a[3]), "r"(b0), "r"(b1));
}

// 64-row bf16 tile: row r = 512B, 32 units of 16B, low-3-bit XOR swizzle
__device__ __forceinline__ uint32_t xoff(int r, int j) {
    return (uint32_t)((r << 9) + (((j & 24) | ((j ^ r) & 7)) << 4));
}

// smem map (bytes)
#define SM_XS  0                       // 64*512 = 32768
#define SM_ES  32768                   // 2 * 32768
#define SM_SC  (SM_ES + 2 * 32768)     // 2 * 256B c chunks
#define SM_SS  (SM_SC + 512)           // 64 * 4
#define SM_RM  (SM_SS + 256)           // 64 * 4
#define SM_SI  (SM_RM + 256)           // 64 * 4 (final indices)
#define SM_DR  (SM_SI + 256)           // 8 doubles
#define SM_FL  (SM_DR + 64)            // last-block flag
#define SM_TOT (SM_FL + 16)

__device__ __forceinline__ unsigned long long exact_pack(
        const float* xr, const float* emb, float Sv, unsigned int k) {
    const float* er = emb + (size_t)k * DIM;
    float m = 0.0f;
    #pragma unroll 4
    for (int i = 0; i < 64; i++) {
        float4 xv = __ldg((const float4*)xr + i);
        float4 ev = __ldg((const float4*)er + i);
        m = __fmaf_rn(xv.x, ev.x, m);
        m = __fmaf_rn(xv.y, ev.y, m);
        m = __fmaf_rn(xv.z, ev.z, m);
        m = __fmaf_rn(xv.w, ev.w, m);
    }
    float d = __fadd_rn(__fmaf_rn(-2.0f, m, Sv), g_c[k]);
    return ((unsigned long long)__float_as_uint(d) << 32) | k;
}

__global__ __launch_bounds__(256, 2) void k_gemm(const float* __restrict__ x,
                                                 const float* __restrict__ emb,
                                                 float* __restrict__ out,
                                                 float* __restrict__ outIdx,
                                                 int N, int K) {
    extern __shared__ char smem[];
    const uint32_t sb = (uint32_t)__cvta_generic_to_shared(smem);
    float*  sS   = (float*)(smem + SM_SS);
    int*    srm  = (int*)  (smem + SM_RM);
    int*    sidx = (int*)  (smem + SM_SI);
    double* sred = (double*)(smem + SM_DR);
    int*    sfl  = (int*)  (smem + SM_FL);

    const int tid  = threadIdx.x;
    const int lane = tid & 31, wid = tid >> 5;
    const int tile = blockIdx.x >> 1;
    const int rb   = tile * BM;
    const int koff = (blockIdx.x & 1) * (K / KSPL);
    const int nch  = K / KSPL / BN;

    if (tid < BM) { srm[tid] = 0x7f7fffff; sS[tid] = g_S[rb + tid]; }

    // preload x tile + e chunk 0 + c chunk 0
    for (int i = tid; i < BM * 32; i += 256) {
        int r = i >> 5, j = i & 31;
        cpa16(sb + SM_XS + xoff(r, j), g_xb + (size_t)(rb + r) * DIM + j * 8);
        cpa16(sb + SM_ES + xoff(r, j), g_eb + (size_t)(koff + r) * DIM + j * 8);
    }
    if (tid < 16) cpa16(sb + SM_SC + tid * 16, g_c + koff + tid * 4);
    asm volatile("cp.async.commit_group;\n");

    const int mi = wid >> 2;       // 0..1 : 32-row group
    const int ni = wid & 3;        // 0..3 : 16-col group
    const int g  = lane >> 2, t = lane & 3;

    for (int ci = 0; ci < nch; ci++) {
        const int buf = ci & 1;
        asm volatile("cp.async.wait_group 0;\n");
        __syncthreads();

        if (ci + 1 < nch) {
            const int nb = (ci + 1) & 1;
            for (int i = tid; i < BN * 32; i += 256) {
                int r = i >> 5, j = i & 31;
                cpa16(sb + SM_ES + nb * 32768 + xoff(r, j),
                      g_eb + (size_t)(koff + (ci + 1) * BN + r) * DIM + j * 8);
            }
            if (tid < 16) cpa16(sb + SM_SC + nb * 256 + tid * 16,
                                g_c + koff + (ci + 1) * BN + tid * 4);
            asm volatile("cp.async.commit_group;\n");
        }

        float acc[2][2][4];
        #pragma unroll
        for (int mt = 0; mt < 2; mt++)
            #pragma unroll
            for (int nf = 0; nf < 2; nf++)
                #pragma unroll
                for (int q = 0; q < 4; q++) acc[mt][nf][q] = 0.0f;

        const uint32_t esb = sb + SM_ES + buf * 32768;
        #pragma unroll
        for (int ks = 0; ks < 16; ks++) {
            uint32_t a[2][4], b[4];
            #pragma unroll
            for (int mt = 0; mt < 2; mt++) {
                int r = mi * 32 + mt * 16 + (lane & 7) + ((lane >> 3) & 1) * 8;
                ldsm4(a[mt], sb + SM_XS + xoff(r, ks * 2 + (lane >> 4)));
            }
            {
                int r = ni * 16 + (lane & 7) + (lane >> 4) * 8;
                ldsm4(b, esb + xoff(r, ks * 2 + ((lane >> 3) & 1)));
            }
            #pragma unroll
            for (int mt = 0; mt < 2; mt++) {
                mma16816(acc[mt][0], a[mt], b[0], b[1]);
                mma16816(acc[mt][1], a[mt], b[2], b[3]);
            }
        }

        // distances in place
        const float* scb = (const float*)(smem + SM_SC + buf * 256);
        #pragma unroll
        for (int mt = 0; mt < 2; mt++)
            #pragma unroll
            for (int nf = 0; nf < 2; nf++)
                #pragma unroll
                for (int h = 0; h < 2; h++)
                    #pragma unroll
                    for (int q = 0; q < 2; q++) {
                        const int rl = mi * 32 + mt * 16 + g + h * 8;
                        const int cl = ni * 16 + nf * 8 + 2 * t + q;
                        acc[mt][nf][h * 2 + q] = __fadd_rn(
                            __fmaf_rn(-2.0f, acc[mt][nf][h * 2 + q], sS[rl]),
                            scb[cl]);
                    }

        if (ci == 0) {
            #pragma unroll
            for (int mt = 0; mt < 2; mt++)
                #pragma unroll
                for (int h = 0; h < 2; h++) {
                    const int rl = mi * 32 + mt * 16 + g + h * 8;
                    float lmin = fminf(fminf(acc[mt][0][h * 2], acc[mt][0][h * 2 + 1]),
                                       fminf(acc[mt][1][h * 2], acc[mt][1][h * 2 + 1]));
                    lmin = fminf(lmin, __shfl_xor_sync(0xffffffffu, lmin, 1));
                    lmin = fminf(lmin, __shfl_xor_sync(0xffffffffu, lmin, 2));
                    if (t == 0) atomicMin(&srm[rl], __float_as_int(lmin));
                }
            __syncthreads();
        }
        const int cb = koff + ci * BN + ni * 16;
        #pragma unroll
        for (int mt = 0; mt < 2; mt++)
            #pragma unroll
            for (int h = 0; h < 2; h++) {
                const int rl  = mi * 32 + mt * 16 + g + h * 8;
                const float rmw = __int_as_float(srm[rl]) + MG;
                float lmin = FLT_MAX;
                #pragma unroll
                for (int nf = 0; nf < 2; nf++)
                    #pragma unroll
                    for (int q = 0; q < 2; q++) {
                        float dist = acc[mt][nf][h * 2 + q];
                        lmin = fminf(lmin, dist);
                        if (dist <= rmw) {
                            unsigned int pos = atomicAdd(&g_cnt[rb + rl], 1u);
                            if (pos < CAP)
                                g_cand[(size_t)(rb + rl) * CAP + pos] =
                                    ((unsigned long long)__float_as_uint(dist) << 32)
                                    | (unsigned int)(cb + nf * 8 + 2 * t + q);
                        }
                    }
                if (ci > 0) {
                    lmin = fminf(lmin, __shfl_xor_sync(0xffffffffu, lmin, 1));
                    lmin = fminf(lmin, __shfl_xor_sync(0xffffffffu, lmin, 2));
                    if (t == 0) atomicMin(&srm[rl], __float_as_int(lmin));
                }
            }
    }
    __syncthreads();
    if (tid < BM) atomicMin(&g_rm[rb + tid], srm[tid]);

    // ---- last-block-done gate: 2nd finisher of this row tile runs the tail ----
    __threadfence();
    __syncthreads();
    if (tid == 0) {
        unsigned int old = atomicAdd(&g_done[tile], 1u);
        *sfl = (old == KSPL - 1);
    }
    __syncthreads();
    if (!*sfl) return;
    __threadfence();

    // ---- fused tail 1: exact rescore (one warp per row, 8 rows/warp) ----
    for (int rr = wid; rr < BM; rr += 8) {
        const int n = rb + rr;
        const unsigned int cnt = g_cnt[n];
        const float Sv  = sS[rr];
        const float thr = __int_as_float(g_rm[n]) + MG;
        const float* xr = x + (size_t)n * DIM;
        unsigned long long best = 0xffffffffffffffffULL;
        if (cnt <= CAP) {
            for (unsigned int e = lane; e < cnt; e += 32) {
                unsigned long long ent = g_cand[(size_t)n * CAP + e];
                float dt = __uint_as_float((unsigned int)(ent >> 32));
                if (dt > thr) continue;
                unsigned long long v =
                    exact_pack(xr, emb, Sv, (unsigned int)(ent & 0xffffffffu));
                if (v < best) best = v;
            }
        } else {  // overflow fallback: exact full scan over all K codes
            for (int k = lane; k < K; k += 32) {
                unsigned long long v = exact_pack(xr, emb, Sv, (unsigned int)k);
                if (v < best) best = v;
            }
        }
        #pragma unroll
        for (int o = 16; o; o >>= 1) {
            unsigned long long v = __shfl_xor_sync(0xffffffffu, best, o);
            if (v < best) best = v;
        }
        if (lane == 0) sidx[rr] = (int)(best & 0xffffffffu);
    }
    __syncthreads();

    // ---- fused tail 2: quantized output + loss partial + indices ----
    double ls = 0.0;
    for (int rr = wid; rr < BM; rr += 8) {
        const int n = rb + rr;
        const int idx = sidx[rr];
        if (lane == 0 && outIdx != nullptr) outIdx[n] = (float)idx;
        const float4* xv4 = (const float4*)(x + (size_t)n * DIM);
        const float4* ev4 = (const float4*)(emb + (size_t)idx * DIM);
        float4* ov4 = (float4*)(out + (size_t)n * DIM);
        for (int i = lane; i < 64; i += 32) {
            float4 xv = __ldg(xv4 + i);
            float4 ev = __ldg(ev4 + i);
            float d0 = __fsub_rn(ev.x, xv.x), d1 = __fsub_rn(ev.y, xv.y);
            float d2 = __fsub_rn(ev.z, xv.z), d3 = __fsub_rn(ev.w, xv.w);
            float4 o;
            o.x = __fadd_rn(xv.x, d0); o.y = __fadd_rn(xv.y, d1);
            o.z = __fadd_rn(xv.z, d2); o.w = __fadd_rn(xv.w, d3);
            ov4[i] = o;
            ls += (double)__fmul_rn(d0, d0) + (double)__fmul_rn(d1, d1)
                + (double)__fmul_rn(d2, d2) + (double)__fmul_rn(d3, d3);
        }
    }
    #pragma unroll
    for (int o = 16; o; o >>= 1) ls += __shfl_xor_sync(0xffffffffu, ls, o);
    if (lane == 0) sred[wid] = ls;
    __syncthreads();
    if (tid == 0) {
        double s = 0.0;
        #pragma unroll
        for (int w = 0; w < 8; w++) s += sred[w];
        atomicAdd(&g_acc, s);
    }
}

__global__ void k_fin(float* __restrict__ out, int N) {
    double m = g_acc / ((double)N * (double)DIM);
    float L = (float)m;
    out[(size_t)N * DIM] = __fadd_rn(L, __fmul_rn(0.25f, L));
}

// ---------------------------------------------------------------------------
extern "C" void kernel_launch(void* const* d_in, const int* in_sizes, int n_in,
                              void* d_out, int out_size) {
    const float* x   = (const float*)d_in[0];
    const float* emb = (const float*)d_in[1];
    const int N = in_sizes[0] / DIM;
    const int K = in_sizes[1] / DIM;
    float* out = (float*)d_out;

    const long long Nq = (long long)N * DIM;
    const bool has_loss = (long long)out_size > Nq;
    const bool has_idx  = (long long)out_size >= Nq + 1 + N;
    float* outIdx = has_idx ? out + Nq + 1 : nullptr;

    cudaFuncSetAttribute(k_gemm, cudaFuncAttributeMaxDynamicSharedMemorySize,
                         SM_TOT);

    k_prep_e<<<(K + 255) / 256, 256>>>(emb, K);
    k_prep_x<<<(N + 255) / 256, 256>>>(x, N);
    k_gemm<<<(N / BM) * KSPL, 256, SM_TOT>>>(x, emb, out, outIdx, N, K);
    if (has_loss) k_fin<<<1, 1>>>(out, N);
}

// round 12
// speedup vs baseline: 1.8401x; 1.0428x over previous
#include <cuda_runtime.h>
#include <cuda_bf16.h>
#include <cstdint>
#include <cfloat>

// VectorQuantizer: x [N,256] fp32, emb [K,256] fp32.
// Out (fp32): quantized [N*256] | loss [1] | indices [N].
// R12 = R8 (best: bf16 f32-accum mma prefilter + fused exact tail), with
// launch order arranged so ncu's skip-window lands on k_gemm (4th launch).

#define DIM   256
#define NMAX  65536
#define KMAX  4096
#define CAP   128
#define MG    2e-3f
#define BM    64
#define BN    64
#define NCH   (KMAX / BN)

__device__ __align__(16) float  g_S[NMAX];
__device__ __align__(16) float  g_c[KMAX];
__device__ unsigned int   g_cnt[NMAX];
__device__ unsigned long long g_cand[(size_t)NMAX * CAP];
__device__ __align__(16) __nv_bfloat16 g_xb[(size_t)NMAX * DIM];
__device__ __align__(16) __nv_bfloat16 g_eb[(size_t)KMAX * DIM];
__device__ double         g_acc;

// ---------------------------------------------------------------------------
__global__ __launch_bounds__(256) void k_prep_x(const float* __restrict__ x, int N) {
    int n = blockIdx.x * blockDim.x + threadIdx.x;
    if (n >= N) return;
    g_cnt[n] = 0u;
    const float4* xr = (const float4*)(x + (size_t)n * DIM);
    __nv_bfloat162* dst = (__nv_bfloat162*)(g_xb + (size_t)n * DIM);
    float s = 0.0f;
    #pragma unroll 8
    for (int i = 0; i < 64; i++) {
        float4 v = __ldg(xr + i);
        s = __fadd_rn(s, __fmul_rn(v.x, v.x));
        s = __fadd_rn(s, __fmul_rn(v.y, v.y));
        s = __fadd_rn(s, __fmul_rn(v.z, v.z));
        s = __fadd_rn(s, __fmul_rn(v.w, v.w));
        dst[2 * i + 0] = __floats2bfloat162_rn(v.x, v.y);
        dst[2 * i + 1] = __floats2bfloat162_rn(v.z, v.w);
    }
    g_S[n] = s;
}

__global__ __launch_bounds__(256) void k_prep_e(const float* __restrict__ emb, int K) {
    int k = blockIdx.x * blockDim.x + threadIdx.x;
    if (k >= K) return;
    const float4* er = (const float4*)(emb + (size_t)k * DIM);
    __nv_bfloat162* dst = (__nv_bfloat162*)(g_eb + (size_t)k * DIM);
    float s = 0.0f;
    #pragma unroll 8
    for (int i = 0; i < 64; i++) {
        float4 v = __ldg(er + i);
        s = __fadd_rn(s, __fmul_rn(v.x, v.x));
        s = __fadd_rn(s, __fmul_rn(v.y, v.y));
        s = __fadd_rn(s, __fmul_rn(v.z, v.z));
        s = __fadd_rn(s, __fmul_rn(v.w, v.w));
        dst[2 * i + 0] = __floats2bfloat162_rn(v.x, v.y);
        dst[2 * i + 1] = __floats2bfloat162_rn(v.z, v.w);
    }
    g_c[k] = s;
}

__global__ void k_zero() { g_acc = 0.0; }

// ---------------------------------------------------------------------------
__device__ __forceinline__ void cpa16(uint32_t s, const void* g) {
    asm volatile("cp.async.cg.shared.global [%0], [%1], 16;\n" :: "r"(s), "l"(g));
}
__device__ __forceinline__ void ldsm4(uint32_t* r, uint32_t a) {
    asm volatile("ldmatrix.sync.aligned.m8n8.x4.shared.b16 {%0,%1,%2,%3}, [%4];"
        : "=r"(r[0]), "=r"(r[1]), "=r"(r[2]), "=r"(r[3]) : "r"(a));
}
__device__ __forceinline__ void mma16816(float* d, const uint32_t* a,
                                         uint32_t b0, uint32_t b1) {
    asm volatile("mma.sync.aligned.m16n8k16.row.col.f32.bf16.bf16.f32 "
        "{%0,%1,%2,%3}, {%4,%5,%6,%7}, {%8,%9}, {%0,%1,%2,%3};"
        : "+f"(d[0]), "+f"(d[1]), "+f"(d[2]), "+f"(d[3])
        : "r"(a[0]), "r"(a[1]), "r"(a[2]), "r"(a[3]), "r"(b0), "r"(b1));
}

// 64-row bf16 tile: row r = 512B, 32 units of 16B, low-3-bit XOR swizzle
__device__ __forceinline__ uint32_t xoff(int r, int j) {
    return (uint32_t)((r << 9) + (((j & 24) | ((j ^ r) & 7)) << 4));
}

// smem map (bytes)
#define SM_XS  0                       // 64*512 = 32768
#define SM_ES  32768                   // 2 * 32768
#define SM_SC  (SM_ES + 2 * 32768)     // 2 * 256B c chunks
#define SM_SS  (SM_SC + 512)           // 64 * 4
#define SM_RM  (SM_SS + 256)           // 64 * 4
#define SM_SI  (SM_RM + 256)           // 64 * 4 (final indices)
#define SM_DR  (SM_SI + 256)           // 8 doubles
#define SM_TOT (SM_DR + 64)

__device__ __forceinline__ unsigned long long exact_pack(
        const float* xr, const float* emb, float Sv, unsigned int k) {
    const float* er = emb + (size_t)k * DIM;
    float m = 0.0f;
    #pragma unroll 4
    for (int i = 0; i < 64; i++) {
        float4 xv = __ldg((const float4*)xr + i);
        float4 ev = __ldg((const float4*)er + i);
        m = __fmaf_rn(xv.x, ev.x, m);
        m = __fmaf_rn(xv.y, ev.y, m);
        m = __fmaf_rn(xv.z, ev.z, m);
        m = __fmaf_rn(xv.w, ev.w, m);
    }
    float d = __fadd_rn(__fmaf_rn(-2.0f, m, Sv), g_c[k]);
    return ((unsigned long long)__float_as_uint(d) << 32) | k;
}

__global__ __launch_bounds__(256, 2) void k_gemm(const float* __restrict__ x,
                                                 const float* __restrict__ emb,
                                                 float* __restrict__ out,
                                                 float* __restrict__ outIdx,
                                                 int N, int K) {
    extern __shared__ char smem[];
    const uint32_t sb = (uint32_t)__cvta_generic_to_shared(smem);
    float*  sS   = (float*)(smem + SM_SS);
    int*    srm  = (int*)  (smem + SM_RM);
    int*    sidx = (int*)  (smem + SM_SI);
    double* sred = (double*)(smem + SM_DR);

    const int tid  = threadIdx.x;
    const int lane = tid & 31, wid = tid >> 5;
    const int rb   = blockIdx.x * BM;

    if (tid < BM) { srm[tid] = 0x7f7fffff; sS[tid] = g_S[rb + tid]; }

    // preload x tile + e chunk 0 + c chunk 0
    for (int i = tid; i < BM * 32; i += 256) {
        int r = i >> 5, j = i & 31;
        cpa16(sb + SM_XS + xoff(r, j), g_xb + (size_t)(rb + r) * DIM + j * 8);
        cpa16(sb + SM_ES + xoff(r, j), g_eb + (size_t)r * DIM + j * 8);
    }
    if (tid < 16) cpa16(sb + SM_SC + tid * 16, g_c + tid * 4);
    asm volatile("cp.async.commit_group;\n");

    const int mi = wid >> 2;       // 0..1 : 32-row group
    const int ni = wid & 3;        // 0..3 : 16-col group
    const int g  = lane >> 2, t = lane & 3;

    for (int ci = 0; ci < NCH; ci++) {
        const int buf = ci & 1;
        asm volatile("cp.async.wait_group 0;\n");
        __syncthreads();

        // prefetch chunk ci+1 (overlaps this chunk's compute)
        if (ci + 1 < NCH) {
            const int nb = (ci + 1) & 1;
            for (int i = tid; i < BN * 32; i += 256) {
                int r = i >> 5, j = i & 31;
                cpa16(sb + SM_ES + nb * 32768 + xoff(r, j),
                      g_eb + (size_t)((ci + 1) * BN + r) * DIM + j * 8);
            }
            if (tid < 16) cpa16(sb + SM_SC + nb * 256 + tid * 16,
                                g_c + (ci + 1) * BN + tid * 4);
            asm volatile("cp.async.commit_group;\n");
        }

        float acc[2][2][4];
        #pragma unroll
        for (int mt = 0; mt < 2; mt++)
            #pragma unroll
            for (int nf = 0; nf < 2; nf++)
                #pragma unroll
                for (int q = 0; q < 4; q++) acc[mt][nf][q] = 0.0f;

        const uint32_t esb = sb + SM_ES + buf * 32768;
        #pragma unroll
        for (int ks = 0; ks < 16; ks++) {
            uint32_t a[2][4], b[4];
            #pragma unroll
            for (int mt = 0; mt < 2; mt++) {
                int r = mi * 32 + mt * 16 + (lane & 7) + ((lane >> 3) & 1) * 8;
                ldsm4(a[mt], sb + SM_XS + xoff(r, ks * 2 + (lane >> 4)));
            }
            {
                int r = ni * 16 + (lane & 7) + (lane >> 4) * 8;
                ldsm4(b, esb + xoff(r, ks * 2 + ((lane >> 3) & 1)));
            }
            #pragma unroll
            for (int mt = 0; mt < 2; mt++) {
                mma16816(acc[mt][0], a[mt], b[0], b[1]);
                mma16816(acc[mt][1], a[mt], b[2], b[3]);
            }
        }

        // distances in place: acc <- fadd(fma(-2,acc,S), c)
        const float* scb = (const float*)(smem + SM_SC + buf * 256);
        #pragma unroll
        for (int mt = 0; mt < 2; mt++)
            #pragma unroll
            for (int nf = 0; nf < 2; nf++)
                #pragma unroll
                for (int h = 0; h < 2; h++)
                    #pragma unroll
                    for (int q = 0; q < 2; q++) {
                        const int rl = mi * 32 + mt * 16 + g + h * 8;
                        const int cl = ni * 16 + nf * 8 + 2 * t + q;
                        acc[mt][nf][h * 2 + q] = __fadd_rn(
                            __fmaf_rn(-2.0f, acc[mt][nf][h * 2 + q], sS[rl]),
                            scb[cl]);
                    }

        const int cbase = ci * BN + ni * 16;
        if (ci == 0) {
            // two-phase for the first chunk (running min not yet seeded)
            #pragma unroll
            for (int mt = 0; mt < 2; mt++)
                #pragma unroll
                for (int h = 0; h < 2; h++) {
                    const int rl = mi * 32 + mt * 16 + g + h * 8;
                    float lmin = fminf(fminf(acc[mt][0][h * 2], acc[mt][0][h * 2 + 1]),
                                       fminf(acc[mt][1][h * 2], acc[mt][1][h * 2 + 1]));
                    lmin = fminf(lmin, __shfl_xor_sync(0xffffffffu, lmin, 1));
                    lmin = fminf(lmin, __shfl_xor_sync(0xffffffffu, lmin, 2));
                    if (t == 0) atomicMin(&srm[rl], __float_as_int(lmin));
                }
            __syncthreads();
        }
        // appends vs (possibly stale) running min — superset-safe
        #pragma unroll
        for (int mt = 0; mt < 2; mt++)
            #pragma unroll
            for (int h = 0; h < 2; h++) {
                const int rl  = mi * 32 + mt * 16 + g + h * 8;
                const float rmw = __int_as_float(srm[rl]) + MG;
                float lmin = FLT_MAX;
                #pragma unroll
                for (int nf = 0; nf < 2; nf++)
                    #pragma unroll
                    for (int q = 0; q < 2; q++) {
                        float dist = acc[mt][nf][h * 2 + q];
                        lmin = fminf(lmin, dist);
                        if (dist <= rmw) {
                            unsigned int pos = atomicAdd(&g_cnt[rb + rl], 1u);
                            if (pos < CAP)
                                g_cand[(size_t)(rb + rl) * CAP + pos] =
                                    ((unsigned long long)__float_as_uint(dist) << 32)
                                    | (unsigned int)(cbase + nf * 8 + 2 * t + q);
                        }
                    }
                if (ci > 0) {   // chunk 0 already folded its min in phase A
                    lmin = fminf(lmin, __shfl_xor_sync(0xffffffffu, lmin, 1));
                    lmin = fminf(lmin, __shfl_xor_sync(0xffffffffu, lmin, 2));
                    if (t == 0) atomicMin(&srm[rl], __float_as_int(lmin));
                }
            }
    }
    __syncthreads();

    // ---- fused tail 1: exact rescore (one warp per row, 8 rows/warp) ----
    for (int rr = wid; rr < BM; rr += 8) {
        const int n = rb + rr;
        const unsigned int cnt = g_cnt[n];
        const float Sv  = sS[rr];
        const float thr = __int_as_float(srm[rr]) + MG;
        const float* xr = x + (size_t)n * DIM;
        unsigned long long best = 0xffffffffffffffffULL;
        if (cnt <= CAP) {
            for (unsigned int e = lane; e < cnt; e += 32) {
                unsigned long long ent = g_cand[(size_t)n * CAP + e];
                float dt = __uint_as_float((unsigned int)(ent >> 32));
                if (dt > thr) continue;
                unsigned long long v =
                    exact_pack(xr, emb, Sv, (unsigned int)(ent & 0xffffffffu));
                if (v < best) best = v;
            }
        } else {  // overflow fallback: exact full scan
            for (int k = lane; k < K; k += 32) {
                unsigned long long v = exact_pack(xr, emb, Sv, (unsigned int)k);
                if (v < best) best = v;
            }
        }
        #pragma unroll
        for (int o = 16; o; o >>= 1) {
            unsigned long long v = __shfl_xor_sync(0xffffffffu, best, o);
            if (v < best) best = v;
        }
        if (lane == 0) sidx[rr] = (int)(best & 0xffffffffu);
    }
    __syncthreads();

    // ---- fused tail 2: quantized output + loss partial + indices ----
    double ls = 0.0;
    for (int rr = wid; rr < BM; rr += 8) {
        const int n = rb + rr;
        const int idx = sidx[rr];
        if (lane == 0 && outIdx != nullptr) outIdx[n] = (float)idx;
        const float4* xv4 = (const float4*)(x + (size_t)n * DIM);
        const float4* ev4 = (const float4*)(emb + (size_t)idx * DIM);
        float4* ov4 = (float4*)(out + (size_t)n * DIM);
        for (int i = lane; i < 64; i += 32) {
            float4 xv = __ldg(xv4 + i);
            float4 ev = __ldg(ev4 + i);
            float d0 = __fsub_rn(ev.x, xv.x), d1 = __fsub_rn(ev.y, xv.y);
            float d2 = __fsub_rn(ev.z, xv.z), d3 = __fsub_rn(ev.w, xv.w);
            float4 o;
            o.x = __fadd_rn(xv.x, d0); o.y = __fadd_rn(xv.y, d1);
            o.z = __fadd_rn(xv.z, d2); o.w = __fadd_rn(xv.w, d3);
            ov4[i] = o;
            ls += (double)__fmul_rn(d0, d0) + (double)__fmul_rn(d1, d1)
                + (double)__fmul_rn(d2, d2) + (double)__fmul_rn(d3, d3);
        }
    }
    #pragma unroll
    for (int o = 16; o; o >>= 1) ls += __shfl_xor_sync(0xffffffffu, ls, o);
    if (lane == 0) sred[wid] = ls;
    __syncthreads();
    if (tid == 0) {
        double s = 0.0;
        #pragma unroll
        for (int w = 0; w < 8; w++) s += sred[w];
        atomicAdd(&g_acc, s);
    }
}

__global__ void k_fin(float* __restrict__ out, int N) {
    double m = g_acc / ((double)N * (double)DIM);
    float L = (float)m;
    out[(size_t)N * DIM] = __fadd_rn(L, __fmul_rn(0.25f, L));
}

// ---------------------------------------------------------------------------
extern "C" void kernel_launch(void* const* d_in, const int* in_sizes, int n_in,
                              void* d_out, int out_size) {
    const float* x   = (const float*)d_in[0];
    const float* emb = (const float*)d_in[1];
    const int N = in_sizes[0] / DIM;
    const int K = in_sizes[1] / DIM;
    float* out = (float*)d_out;

    const long long Nq = (long long)N * DIM;
    const bool has_loss = (long long)out_size > Nq;
    const bool has_idx  = (long long)out_size >= Nq + 1 + N;
    float* outIdx = has_idx ? out + Nq + 1 : nullptr;

    cudaFuncSetAttribute(k_gemm, cudaFuncAttributeMaxDynamicSharedMemorySize,
                         SM_TOT);

    k_prep_e<<<(K + 255) / 256, 256>>>(emb, K);      // 1
    k_prep_x<<<(N + 255) / 256, 256>>>(x, N);        // 2
    k_zero<<<1, 1>>>();                              // 3
    k_gemm<<<N / BM, 256, SM_TOT>>>(x, emb, out, outIdx, N, K);  // 4 <- profiled
    if (has_loss) k_fin<<<1, 1>>>(out, N);           // 5
}

// round 13
// speedup vs baseline: 1.9623x; 1.0664x over previous
#include <cuda_runtime.h>
#include <cuda_bf16.h>
#include <cstdint>
#include <cfloat>

// VectorQuantizer: x [N,256] fp32, emb [K,256] fp32.
// Out (fp32): quantized [N*256] | loss [1] | indices [N].
// R13: occupancy fix per R12 profile (tensor 20%, occ 24% -> latency-bound).
// BM=64/BN=32, single-buffered E, 4 blocks/SM (32 warps), 16x16 warp tiles.

#define DIM   256
#define NMAX  65536
#define KMAX  4096
#define CAP   128
#define MG    2e-3f
#define BM    64
#define BN    32
#define NCH   (KMAX / BN)

__device__ __align__(16) float  g_S[NMAX];
__device__ __align__(16) float  g_c[KMAX];
__device__ unsigned int   g_cnt[NMAX];
__device__ unsigned long long g_cand[(size_t)NMAX * CAP];
__device__ __align__(16) __nv_bfloat16 g_xb[(size_t)NMAX * DIM];
__device__ __align__(16) __nv_bfloat16 g_eb[(size_t)KMAX * DIM];
__device__ double         g_acc;

// ---------------------------------------------------------------------------
__global__ __launch_bounds__(256) void k_prep_x(const float* __restrict__ x, int N) {
    int n = blockIdx.x * blockDim.x + threadIdx.x;
    if (n >= N) return;
    g_cnt[n] = 0u;
    const float4* xr = (const float4*)(x + (size_t)n * DIM);
    __nv_bfloat162* dst = (__nv_bfloat162*)(g_xb + (size_t)n * DIM);
    float s = 0.0f;
    #pragma unroll 8
    for (int i = 0; i < 64; i++) {
        float4 v = __ldg(xr + i);
        s = __fadd_rn(s, __fmul_rn(v.x, v.x));
        s = __fadd_rn(s, __fmul_rn(v.y, v.y));
        s = __fadd_rn(s, __fmul_rn(v.z, v.z));
        s = __fadd_rn(s, __fmul_rn(v.w, v.w));
        dst[2 * i + 0] = __floats2bfloat162_rn(v.x, v.y);
        dst[2 * i + 1] = __floats2bfloat162_rn(v.z, v.w);
    }
    g_S[n] = s;
}

__global__ __launch_bounds__(256) void k_prep_e(const float* __restrict__ emb, int K) {
    int k = blockIdx.x * blockDim.x + threadIdx.x;
    if (k >= K) return;
    const float4* er = (const float4*)(emb + (size_t)k * DIM);
    __nv_bfloat162* dst = (__nv_bfloat162*)(g_eb + (size_t)k * DIM);
    float s = 0.0f;
    #pragma unroll 8
    for (int i = 0; i < 64; i++) {
        float4 v = __ldg(er + i);
        s = __fadd_rn(s, __fmul_rn(v.x, v.x));
        s = __fadd_rn(s, __fmul_rn(v.y, v.y));
        s = __fadd_rn(s, __fmul_rn(v.z, v.z));
        s = __fadd_rn(s, __fmul_rn(v.w, v.w));
        dst[2 * i + 0] = __floats2bfloat162_rn(v.x, v.y);
        dst[2 * i + 1] = __floats2bfloat162_rn(v.z, v.w);
    }
    g_c[k] = s;
}

__global__ void k_zero() { g_acc = 0.0; }

// ---------------------------------------------------------------------------
__device__ __forceinline__ void cpa16(uint32_t s, const void* g) {
    asm volatile("cp.async.cg.shared.global [%0], [%1], 16;\n" :: "r"(s), "l"(g));
}
__device__ __forceinline__ void ldsm4(uint32_t* r, uint32_t a) {
    asm volatile("ldmatrix.sync.aligned.m8n8.x4.shared.b16 {%0,%1,%2,%3}, [%4];"
        : "=r"(r[0]), "=r"(r[1]), "=r"(r[2]), "=r"(r[3]) : "r"(a));
}
__device__ __forceinline__ void mma16816(float* d, const uint32_t* a,
                                         uint32_t b0, uint32_t b1) {
    asm volatile("mma.sync.aligned.m16n8k16.row.col.f32.bf16.bf16.f32 "
        "{%0,%1,%2,%3}, {%4,%5,%6,%7}, {%8,%9}, {%0,%1,%2,%3};"
        : "+f"(d[0]), "+f"(d[1]), "+f"(d[2]), "+f"(d[3])
        : "r"(a[0]), "r"(a[1]), "r"(a[2]), "r"(a[3]), "r"(b0), "r"(b1));
}

// bf16 tile: row r = 512B (256 dims), 32 units of 16B, low-3-bit XOR swizzle
__device__ __forceinline__ uint32_t xoff(int r, int j) {
    return (uint32_t)((r << 9) + (((j & 24) | ((j ^ r) & 7)) << 4));
}

// smem map (bytes)
#define SM_XS  0                       // 64*512 = 32768
#define SM_ES  32768                   // 32*512 = 16384 (single buffer)
#define SM_SC  (SM_ES + 16384)         // 2 x 256B c chunks (32 floats each)
#define SM_SS  (SM_SC + 512)           // 64 * 4
#define SM_RM  (SM_SS + 256)           // 64 * 4
#define SM_SI  (SM_RM + 256)           // 64 * 4 (final indices)
#define SM_DR  (SM_SI + 256)           // 8 doubles
#define SM_TOT (SM_DR + 64)

__device__ __forceinline__ unsigned long long exact_pack(
        const float* xr, const float* emb, float Sv, unsigned int k) {
    const float* er = emb + (size_t)k * DIM;
    float m = 0.0f;
    #pragma unroll 4
    for (int i = 0; i < 64; i++) {
        float4 xv = __ldg((const float4*)xr + i);
        float4 ev = __ldg((const float4*)er + i);
        m = __fmaf_rn(xv.x, ev.x, m);
        m = __fmaf_rn(xv.y, ev.y, m);
        m = __fmaf_rn(xv.z, ev.z, m);
        m = __fmaf_rn(xv.w, ev.w, m);
    }
    float d = __fadd_rn(__fmaf_rn(-2.0f, m, Sv), g_c[k]);
    return ((unsigned long long)__float_as_uint(d) << 32) | k;
}

__global__ __launch_bounds__(256, 4) void k_gemm(const float* __restrict__ x,
                                                 const float* __restrict__ emb,
                                                 float* __restrict__ out,
                                                 float* __restrict__ outIdx,
                                                 int N, int K) {
    extern __shared__ char smem[];
    const uint32_t sb = (uint32_t)__cvta_generic_to_shared(smem);
    float*  sS   = (float*)(smem + SM_SS);
    int*    srm  = (int*)  (smem + SM_RM);
    int*    sidx = (int*)  (smem + SM_SI);
    double* sred = (double*)(smem + SM_DR);

    const int tid  = threadIdx.x;
    const int lane = tid & 31, wid = tid >> 5;
    const int rb   = blockIdx.x * BM;

    if (tid < BM) { srm[tid] = 0x7f7fffff; sS[tid] = g_S[rb + tid]; }

    // preload x tile + e chunk 0 + c chunk 0
    for (int i = tid; i < BM * 32; i += 256) {
        int r = i >> 5, j = i & 31;
        cpa16(sb + SM_XS + xoff(r, j), g_xb + (size_t)(rb + r) * DIM + j * 8);
    }
    for (int i = tid; i < BN * 32; i += 256) {
        int r = i >> 5, j = i & 31;
        cpa16(sb + SM_ES + xoff(r, j), g_eb + (size_t)r * DIM + j * 8);
    }
    if (tid < 8) cpa16(sb + SM_SC + tid * 16, g_c + tid * 4);
    asm volatile("cp.async.commit_group;\n");

    const int mi = wid >> 1;       // 0..3 : 16-row group
    const int ni = wid & 1;        // 0..1 : 16-col group
    const int g  = lane >> 2, t = lane & 3;

    asm volatile("cp.async.wait_group 0;\n");
    __syncthreads();

    for (int ci = 0; ci < NCH; ci++) {
        float acc[2][4];
        #pragma unroll
        for (int nf = 0; nf < 2; nf++)
            #pragma unroll
            for (int q = 0; q < 4; q++) acc[nf][q] = 0.0f;

        #pragma unroll
        for (int ks = 0; ks < 16; ks++) {
            uint32_t a[4], b[4];
            {
                int r = mi * 16 + (lane & 7) + ((lane >> 3) & 1) * 8;
                ldsm4(a, sb + SM_XS + xoff(r, ks * 2 + (lane >> 4)));
            }
            {
                int r = ni * 16 + (lane & 7) + (lane >> 4) * 8;
                ldsm4(b, sb + SM_ES + xoff(r, ks * 2 + ((lane >> 3) & 1)));
            }
            mma16816(acc[0], a, b[0], b[1]);
            mma16816(acc[1], a, b[2], b[3]);
        }

        // all warps done reading the single E buffer
        __syncthreads();

        // issue next chunk's loads; they fly under the epilogue below
        if (ci + 1 < NCH) {
            for (int i = tid; i < BN * 32; i += 256) {
                int r = i >> 5, j = i & 31;
                cpa16(sb + SM_ES + xoff(r, j),
                      g_eb + (size_t)((ci + 1) * BN + r) * DIM + j * 8);
            }
            if (tid < 8) cpa16(sb + SM_SC + ((ci + 1) & 1) * 256 + tid * 16,
                               g_c + (ci + 1) * BN + tid * 4);
            asm volatile("cp.async.commit_group;\n");
        }

        // distances in place: acc <- fadd(fma(-2,acc,S), c)
        const float* scb = (const float*)(smem + SM_SC + (ci & 1) * 256);
        const float Sv = sS[mi * 16 + g];         // row for h=0
        const float Sv2 = sS[mi * 16 + g + 8];    // row for h=1
        #pragma unroll
        for (int nf = 0; nf < 2; nf++) {
            const int cl = ni * 16 + nf * 8 + 2 * t;
            acc[nf][0] = __fadd_rn(__fmaf_rn(-2.0f, acc[nf][0], Sv),  scb[cl]);
            acc[nf][1] = __fadd_rn(__fmaf_rn(-2.0f, acc[nf][1], Sv),  scb[cl + 1]);
            acc[nf][2] = __fadd_rn(__fmaf_rn(-2.0f, acc[nf][2], Sv2), scb[cl]);
            acc[nf][3] = __fadd_rn(__fmaf_rn(-2.0f, acc[nf][3], Sv2), scb[cl + 1]);
        }

        if (ci == 0) {
            // two-phase for the first chunk (running min not yet seeded)
            #pragma unroll
            for (int h = 0; h < 2; h++) {
                const int rl = mi * 16 + g + h * 8;
                float lmin = fminf(fminf(acc[0][h * 2], acc[0][h * 2 + 1]),
                                   fminf(acc[1][h * 2], acc[1][h * 2 + 1]));
                lmin = fminf(lmin, __shfl_xor_sync(0xffffffffu, lmin, 1));
                lmin = fminf(lmin, __shfl_xor_sync(0xffffffffu, lmin, 2));
                if (t == 0) atomicMin(&srm[rl], __float_as_int(lmin));
            }
            __syncthreads();
        }
        // appends vs (possibly stale) running min — superset-safe
        const int cbase = ci * BN + ni * 16;
        #pragma unroll
        for (int h = 0; h < 2; h++) {
            const int rl  = mi * 16 + g + h * 8;
            const float rmw = __int_as_float(srm[rl]) + MG;
            float lmin = FLT_MAX;
            #pragma unroll
            for (int nf = 0; nf < 2; nf++)
                #pragma unroll
                for (int q = 0; q < 2; q++) {
                    float dist = acc[nf][h * 2 + q];
                    lmin = fminf(lmin, dist);
                    if (dist <= rmw) {
                        unsigned int pos = atomicAdd(&g_cnt[rb + rl], 1u);
                        if (pos < CAP)
                            g_cand[(size_t)(rb + rl) * CAP + pos] =
                                ((unsigned long long)__float_as_uint(dist) << 32)
                                | (unsigned int)(cbase + nf * 8 + 2 * t + q);
                    }
                }
            if (ci > 0) {   // chunk 0 already folded its min in phase A
                lmin = fminf(lmin, __shfl_xor_sync(0xffffffffu, lmin, 1));
                lmin = fminf(lmin, __shfl_xor_sync(0xffffffffu, lmin, 2));
                if (t == 0) atomicMin(&srm[rl], __float_as_int(lmin));
            }
        }

        // next chunk's E tile must be resident before the next mma loop
        asm volatile("cp.async.wait_group 0;\n");
        __syncthreads();
    }

    // ---- fused tail 1: exact rescore (one warp per row, 8 rows/warp) ----
    for (int rr = wid; rr < BM; rr += 8) {
        const int n = rb + rr;
        const unsigned int cnt = g_cnt[n];
        const float Sv  = sS[rr];
        const float thr = __int_as_float(srm[rr]) + MG;
        const float* xr = x + (size_t)n * DIM;
        unsigned long long best = 0xffffffffffffffffULL;
        if (cnt <= CAP) {
            for (unsigned int e = lane; e < cnt; e += 32) {
                unsigned long long ent = g_cand[(size_t)n * CAP + e];
                float dt = __uint_as_float((unsigned int)(ent >> 32));
                if (dt > thr) continue;
                unsigned long long v =
                    exact_pack(xr, emb, Sv, (unsigned int)(ent & 0xffffffffu));
                if (v < best) best = v;
            }
        } else {  // overflow fallback: exact full scan
            for (int k = lane; k < K; k += 32) {
                unsigned long long v = exact_pack(xr, emb, Sv, (unsigned int)k);
                if (v < best) best = v;
            }
        }
        #pragma unroll
        for (int o = 16; o; o >>= 1) {
            unsigned long long v = __shfl_xor_sync(0xffffffffu, best, o);
            if (v < best) best = v;
        }
        if (lane == 0) sidx[rr] = (int)(best & 0xffffffffu);
    }
    __syncthreads();

    // ---- fused tail 2: quantized output + loss partial + indices ----
    double ls = 0.0;
    for (int rr = wid; rr < BM; rr += 8) {
        const int n = rb + rr;
        const int idx = sidx[rr];
        if (lane == 0 && outIdx != nullptr) outIdx[n] = (float)idx;
        const float4* xv4 = (const float4*)(x + (size_t)n * DIM);
        const float4* ev4 = (const float4*)(emb + (size_t)idx * DIM);
        float4* ov4 = (float4*)(out + (size_t)n * DIM);
        for (int i = lane; i < 64; i += 32) {
            float4 xv = __ldg(xv4 + i);
            float4 ev = __ldg(ev4 + i);
            float d0 = __fsub_rn(ev.x, xv.x), d1 = __fsub_rn(ev.y, xv.y);
            float d2 = __fsub_rn(ev.z, xv.z), d3 = __fsub_rn(ev.w, xv.w);
            float4 o;
            o.x = __fadd_rn(xv.x, d0); o.y = __fadd_rn(xv.y, d1);
            o.z = __fadd_rn(xv.z, d2); o.w = __fadd_rn(xv.w, d3);
            ov4[i] = o;
            ls += (double)__fmul_rn(d0, d0) + (double)__fmul_rn(d1, d1)
                + (double)__fmul_rn(d2, d2) + (double)__fmul_rn(d3, d3);
        }
    }
    #pragma unroll
    for (int o = 16; o; o >>= 1) ls += __shfl_xor_sync(0xffffffffu, ls, o);
    if (lane == 0) sred[wid] = ls;
    __syncthreads();
    if (tid == 0) {
        double s = 0.0;
        #pragma unroll
        for (int w = 0; w < 8; w++) s += sred[w];
        atomicAdd(&g_acc, s);
    }
}

__global__ void k_fin(float* __restrict__ out, int N) {
    double m = g_acc / ((double)N * (double)DIM);
    float L = (float)m;
    out[(size_t)N * DIM] = __fadd_rn(L, __fmul_rn(0.25f, L));
}

// ---------------------------------------------------------------------------
extern "C" void kernel_launch(void* const* d_in, const int* in_sizes, int n_in,
                              void* d_out, int out_size) {
    const float* x   = (const float*)d_in[0];
    const float* emb = (const float*)d_in[1];
    const int N = in_sizes[0] / DIM;
    const int K = in_sizes[1] / DIM;
    float* out = (float*)d_out;

    const long long Nq = (long long)N * DIM;
    const bool has_loss = (long long)out_size > Nq;
    const bool has_idx  = (long long)out_size >= Nq + 1 + N;
    float* outIdx = has_idx ? out + Nq + 1 : nullptr;

    cudaFuncSetAttribute(k_gemm, cudaFuncAttributeMaxDynamicSharedMemorySize,
                         SM_TOT);

    k_prep_e<<<(K + 255) / 256, 256>>>(emb, K);      // 1
    k_prep_x<<<(N + 255) / 256, 256>>>(x, N);        // 2
    k_zero<<<1, 1>>>();                              // 3
    k_gemm<<<N / BM, 256, SM_TOT>>>(x, emb, out, outIdx, N, K);  // 4 <- profiled
    if (has_loss) k_fin<<<1, 1>>>(out, N);           // 5
}

// round 14
// speedup vs baseline: 2.2208x; 1.1317x over previous
#include <cuda_runtime.h>
#include <cuda_bf16.h>
#include <cstdint>
#include <cfloat>

// VectorQuantizer: x [N,256] fp32, emb [K,256] fp32.
// Out (fp32): quantized [N*256] | loss [1] | indices [N].
// R14: 64x64 block tile, 16x32 warp tiles (0.1875 B/MAC ldsm), single-buffer
// E, 3 blocks/SM. Prefilter margin 2e-3 + fused exact rescore tail (rel_err 0).

#define DIM   256
#define NMAX  65536
#define KMAX  4096
#define CAP   128
#define MG    2e-3f
#define BM    64
#define BN    64
#define NCH   (KMAX / BN)

__device__ __align__(16) float  g_S[NMAX];
__device__ __align__(16) float  g_c[KMAX];
__device__ unsigned int   g_cnt[NMAX];
__device__ unsigned long long g_cand[(size_t)NMAX * CAP];
__device__ __align__(16) __nv_bfloat16 g_xb[(size_t)NMAX * DIM];
__device__ __align__(16) __nv_bfloat16 g_eb[(size_t)KMAX * DIM];
__device__ double         g_acc;

// ---------------------------------------------------------------------------
__global__ __launch_bounds__(256) void k_prep_x(const float* __restrict__ x, int N) {
    int n = blockIdx.x * blockDim.x + threadIdx.x;
    if (n >= N) return;
    g_cnt[n] = 0u;
    const float4* xr = (const float4*)(x + (size_t)n * DIM);
    __nv_bfloat162* dst = (__nv_bfloat162*)(g_xb + (size_t)n * DIM);
    float s = 0.0f;
    #pragma unroll 8
    for (int i = 0; i < 64; i++) {
        float4 v = __ldg(xr + i);
        s = __fadd_rn(s, __fmul_rn(v.x, v.x));
        s = __fadd_rn(s, __fmul_rn(v.y, v.y));
        s = __fadd_rn(s, __fmul_rn(v.z, v.z));
        s = __fadd_rn(s, __fmul_rn(v.w, v.w));
        dst[2 * i + 0] = __floats2bfloat162_rn(v.x, v.y);
        dst[2 * i + 1] = __floats2bfloat162_rn(v.z, v.w);
    }
    g_S[n] = s;
}

__global__ __launch_bounds__(256) void k_prep_e(const float* __restrict__ emb, int K) {
    int k = blockIdx.x * blockDim.x + threadIdx.x;
    if (k >= K) return;
    const float4* er = (const float4*)(emb + (size_t)k * DIM);
    __nv_bfloat162* dst = (__nv_bfloat162*)(g_eb + (size_t)k * DIM);
    float s = 0.0f;
    #pragma unroll 8
    for (int i = 0; i < 64; i++) {
        float4 v = __ldg(er + i);
        s = __fadd_rn(s, __fmul_rn(v.x, v.x));
        s = __fadd_rn(s, __fmul_rn(v.y, v.y));
        s = __fadd_rn(s, __fmul_rn(v.z, v.z));
        s = __fadd_rn(s, __fmul_rn(v.w, v.w));
        dst[2 * i + 0] = __floats2bfloat162_rn(v.x, v.y);
        dst[2 * i + 1] = __floats2bfloat162_rn(v.z, v.w);
    }
    g_c[k] = s;
}

__global__ void k_zero() { g_acc = 0.0; }

// ---------------------------------------------------------------------------
__device__ __forceinline__ void cpa16(uint32_t s, const void* g) {
    asm volatile("cp.async.cg.shared.global [%0], [%1], 16;\n" :: "r"(s), "l"(g));
}
__device__ __forceinline__ void ldsm4(uint32_t* r, uint32_t a) {
    asm volatile("ldmatrix.sync.aligned.m8n8.x4.shared.b16 {%0,%1,%2,%3}, [%4];"
        : "=r"(r[0]), "=r"(r[1]), "=r"(r[2]), "=r"(r[3]) : "r"(a));
}
__device__ __forceinline__ void mma16816(float* d, const uint32_t* a,
                                         uint32_t b0, uint32_t b1) {
    asm volatile("mma.sync.aligned.m16n8k16.row.col.f32.bf16.bf16.f32 "
        "{%0,%1,%2,%3}, {%4,%5,%6,%7}, {%8,%9}, {%0,%1,%2,%3};"
        : "+f"(d[0]), "+f"(d[1]), "+f"(d[2]), "+f"(d[3])
        : "r"(a[0]), "r"(a[1]), "r"(a[2]), "r"(a[3]), "r"(b0), "r"(b1));
}

// bf16 tile: row r = 512B (256 dims), 32 units of 16B, low-3-bit XOR swizzle
__device__ __forceinline__ uint32_t xoff(int r, int j) {
    return (uint32_t)((r << 9) + (((j & 24) | ((j ^ r) & 7)) << 4));
}

// smem map (bytes)
#define SM_XS  0                       // 64*512 = 32768
#define SM_ES  32768                   // 64*512 = 32768 (single buffer)
#define SM_SC  (SM_ES + 32768)         // 2 x 256B c chunks (64 floats each)
#define SM_SS  (SM_SC + 512)           // 64 * 4
#define SM_RM  (SM_SS + 256)           // 64 * 4
#define SM_SI  (SM_RM + 256)           // 64 * 4 (final indices)
#define SM_DR  (SM_SI + 256)           // 8 doubles
#define SM_TOT (SM_DR + 64)

__device__ __forceinline__ unsigned long long exact_pack(
        const float* xr, const float* emb, float Sv, unsigned int k) {
    const float* er = emb + (size_t)k * DIM;
    float m = 0.0f;
    #pragma unroll 4
    for (int i = 0; i < 64; i++) {
        float4 xv = __ldg((const float4*)xr + i);
        float4 ev = __ldg((const float4*)er + i);
        m = __fmaf_rn(xv.x, ev.x, m);
        m = __fmaf_rn(xv.y, ev.y, m);
        m = __fmaf_rn(xv.z, ev.z, m);
        m = __fmaf_rn(xv.w, ev.w, m);
    }
    float d = __fadd_rn(__fmaf_rn(-2.0f, m, Sv), g_c[k]);
    return ((unsigned long long)__float_as_uint(d) << 32) | k;
}

__global__ __launch_bounds__(256, 3) void k_gemm(const float* __restrict__ x,
                                                 const float* __restrict__ emb,
                                                 float* __restrict__ out,
                                                 float* __restrict__ outIdx,
                                                 int N, int K) {
    extern __shared__ char smem[];
    const uint32_t sb = (uint32_t)__cvta_generic_to_shared(smem);
    float*  sS   = (float*)(smem + SM_SS);
    int*    srm  = (int*)  (smem + SM_RM);
    int*    sidx = (int*)  (smem + SM_SI);
    double* sred = (double*)(smem + SM_DR);

    const int tid  = threadIdx.x;
    const int lane = tid & 31, wid = tid >> 5;
    const int rb   = blockIdx.x * BM;

    if (tid < BM) { srm[tid] = 0x7f7fffff; sS[tid] = g_S[rb + tid]; }

    // preload x tile + e chunk 0 + c chunk 0
    for (int i = tid; i < BM * 32; i += 256) {
        int r = i >> 5, j = i & 31;
        cpa16(sb + SM_XS + xoff(r, j), g_xb + (size_t)(rb + r) * DIM + j * 8);
        cpa16(sb + SM_ES + xoff(r, j), g_eb + (size_t)r * DIM + j * 8);
    }
    if (tid < 16) cpa16(sb + SM_SC + tid * 16, g_c + tid * 4);
    asm volatile("cp.async.commit_group;\n");

    const int mi = wid >> 1;       // 0..3 : 16-row group
    const int ni = wid & 1;        // 0..1 : 32-col group
    const int g  = lane >> 2, t = lane & 3;

    asm volatile("cp.async.wait_group 0;\n");
    __syncthreads();

    for (int ci = 0; ci < NCH; ci++) {
        float acc[4][4];               // [nn 8-col group][quad]
        #pragma unroll
        for (int nn = 0; nn < 4; nn++)
            #pragma unroll
            for (int q = 0; q < 4; q++) acc[nn][q] = 0.0f;

        #pragma unroll
        for (int ks = 0; ks < 16; ks++) {
            uint32_t a[4], b[2][4];
            {
                int r = mi * 16 + (lane & 7) + ((lane >> 3) & 1) * 8;
                ldsm4(a, sb + SM_XS + xoff(r, ks * 2 + (lane >> 4)));
            }
            #pragma unroll
            for (int nb2 = 0; nb2 < 2; nb2++) {
                int r = ni * 32 + nb2 * 16 + (lane & 7) + (lane >> 4) * 8;
                ldsm4(b[nb2], sb + SM_ES + xoff(r, ks * 2 + ((lane >> 3) & 1)));
            }
            #pragma unroll
            for (int nb2 = 0; nb2 < 2; nb2++) {
                mma16816(acc[nb2 * 2 + 0], a, b[nb2][0], b[nb2][1]);
                mma16816(acc[nb2 * 2 + 1], a, b[nb2][2], b[nb2][3]);
            }
        }

        // all warps done reading the single E buffer
        __syncthreads();

        // issue next chunk's loads; they fly under the epilogue below
        if (ci + 1 < NCH) {
            for (int i = tid; i < BN * 32; i += 256) {
                int r = i >> 5, j = i & 31;
                cpa16(sb + SM_ES + xoff(r, j),
                      g_eb + (size_t)((ci + 1) * BN + r) * DIM + j * 8);
            }
            if (tid < 16) cpa16(sb + SM_SC + ((ci + 1) & 1) * 256 + tid * 16,
                                g_c + (ci + 1) * BN + tid * 4);
            asm volatile("cp.async.commit_group;\n");
        }

        // distances in place: acc <- fadd(fma(-2,acc,S), c)
        const float* scb = (const float*)(smem + SM_SC + (ci & 1) * 256);
        const float Sv  = sS[mi * 16 + g];
        const float Sv2 = sS[mi * 16 + g + 8];
        #pragma unroll
        for (int nn = 0; nn < 4; nn++) {
            const int cl = ni * 32 + ((nn >> 1) << 4) + ((nn & 1) << 3) + 2 * t;
            acc[nn][0] = __fadd_rn(__fmaf_rn(-2.0f, acc[nn][0], Sv),  scb[cl]);
            acc[nn][1] = __fadd_rn(__fmaf_rn(-2.0f, acc[nn][1], Sv),  scb[cl + 1]);
            acc[nn][2] = __fadd_rn(__fmaf_rn(-2.0f, acc[nn][2], Sv2), scb[cl]);
            acc[nn][3] = __fadd_rn(__fmaf_rn(-2.0f, acc[nn][3], Sv2), scb[cl + 1]);
        }

        if (ci == 0) {
            // two-phase for the first chunk (running min not yet seeded)
            #pragma unroll
            for (int h = 0; h < 2; h++) {
                const int rl = mi * 16 + g + h * 8;
                float lmin = FLT_MAX;
                #pragma unroll
                for (int nn = 0; nn < 4; nn++)
                    #pragma unroll
                    for (int q = 0; q < 2; q++)
                        lmin = fminf(lmin, acc[nn][h * 2 + q]);
                lmin = fminf(lmin, __shfl_xor_sync(0xffffffffu, lmin, 1));
                lmin = fminf(lmin, __shfl_xor_sync(0xffffffffu, lmin, 2));
                if (t == 0) atomicMin(&srm[rl], __float_as_int(lmin));
            }
            __syncthreads();
        }
        // appends vs (possibly stale) running min — superset-safe
        const int cbase = ci * BN + ni * 32;
        #pragma unroll
        for (int h = 0; h < 2; h++) {
            const int rl  = mi * 16 + g + h * 8;
            const float rmw = __int_as_float(srm[rl]) + MG;
            float lmin = FLT_MAX;
            #pragma unroll
            for (int nn = 0; nn < 4; nn++)
                #pragma unroll
                for (int q = 0; q < 2; q++) {
                    float dist = acc[nn][h * 2 + q];
                    lmin = fminf(lmin, dist);
                    if (dist <= rmw) {
                        unsigned int pos = atomicAdd(&g_cnt[rb + rl], 1u);
                        if (pos < CAP)
                            g_cand[(size_t)(rb + rl) * CAP + pos] =
                                ((unsigned long long)__float_as_uint(dist) << 32)
                                | (unsigned int)(cbase + ((nn >> 1) << 4)
                                                 + ((nn & 1) << 3) + 2 * t + q);
                    }
                }
            if (ci > 0) {   // chunk 0 already folded its min in phase A
                lmin = fminf(lmin, __shfl_xor_sync(0xffffffffu, lmin, 1));
                lmin = fminf(lmin, __shfl_xor_sync(0xffffffffu, lmin, 2));
                if (t == 0) atomicMin(&srm[rl], __float_as_int(lmin));
            }
        }

        // next chunk's E tile must be resident before the next mma loop
        asm volatile("cp.async.wait_group 0;\n");
        __syncthreads();
    }

    // ---- fused tail 1: exact rescore (one warp per row, 8 rows/warp) ----
    for (int rr = wid; rr < BM; rr += 8) {
        const int n = rb + rr;
        const unsigned int cnt = g_cnt[n];
        const float Sv  = sS[rr];
        const float thr = __int_as_float(srm[rr]) + MG;
        const float* xr = x + (size_t)n * DIM;
        unsigned long long best = 0xffffffffffffffffULL;
        if (cnt <= CAP) {
            for (unsigned int e = lane; e < cnt; e += 32) {
                unsigned long long ent = g_cand[(size_t)n * CAP + e];
                float dt = __uint_as_float((unsigned int)(ent >> 32));
                if (dt > thr) continue;
                unsigned long long v =
                    exact_pack(xr, emb, Sv, (unsigned int)(ent & 0xffffffffu));
                if (v < best) best = v;
            }
        } else {  // overflow fallback: exact full scan
            for (int k = lane; k < K; k += 32) {
                unsigned long long v = exact_pack(xr, emb, Sv, (unsigned int)k);
                if (v < best) best = v;
            }
        }
        #pragma unroll
        for (int o = 16; o; o >>= 1) {
            unsigned long long v = __shfl_xor_sync(0xffffffffu, best, o);
            if (v < best) best = v;
        }
        if (lane == 0) sidx[rr] = (int)(best & 0xffffffffu);
    }
    __syncthreads();

    // ---- fused tail 2: quantized output + loss partial + indices ----
    double ls = 0.0;
    for (int rr = wid; rr < BM; rr += 8) {
        const int n = rb + rr;
        const int idx = sidx[rr];
        if (lane == 0 && outIdx != nullptr) outIdx[n] = (float)idx;
        const float4* xv4 = (const float4*)(x + (size_t)n * DIM);
        const float4* ev4 = (const float4*)(emb + (size_t)idx * DIM);
        float4* ov4 = (float4*)(out + (size_t)n * DIM);
        for (int i = lane; i < 64; i += 32) {
            float4 xv = __ldg(xv4 + i);
            float4 ev = __ldg(ev4 + i);
            float d0 = __fsub_rn(ev.x, xv.x), d1 = __fsub_rn(ev.y, xv.y);
            float d2 = __fsub_rn(ev.z, xv.z), d3 = __fsub_rn(ev.w, xv.w);
            float4 o;
            o.x = __fadd_rn(xv.x, d0); o.y = __fadd_rn(xv.y, d1);
            o.z = __fadd_rn(xv.z, d2); o.w = __fadd_rn(xv.w, d3);
            ov4[i] = o;
            ls += (double)__fmul_rn(d0, d0) + (double)__fmul_rn(d1, d1)
                + (double)__fmul_rn(d2, d2) + (double)__fmul_rn(d3, d3);
        }
    }
    #pragma unroll
    for (int o = 16; o; o >>= 1) ls += __shfl_xor_sync(0xffffffffu, ls, o);
    if (lane == 0) sred[wid] = ls;
    __syncthreads();
    if (tid == 0) {
        double s = 0.0;
        #pragma unroll
        for (int w = 0; w < 8; w++) s += sred[w];
        atomicAdd(&g_acc, s);
    }
}

__global__ void k_fin(float* __restrict__ out, int N) {
    double m = g_acc / ((double)N * (double)DIM);
    float L = (float)m;
    out[(size_t)N * DIM] = __fadd_rn(L, __fmul_rn(0.25f, L));
}

// ---------------------------------------------------------------------------
extern "C" void kernel_launch(void* const* d_in, const int* in_sizes, int n_in,
                              void* d_out, int out_size) {
    const float* x   = (const float*)d_in[0];
    const float* emb = (const float*)d_in[1];
    const int N = in_sizes[0] / DIM;
    const int K = in_sizes[1] / DIM;
    float* out = (float*)d_out;

    const long long Nq = (long long)N * DIM;
    const bool has_loss = (long long)out_size > Nq;
    const bool has_idx  = (long long)out_size >= Nq + 1 + N;
    float* outIdx = has_idx ? out + Nq + 1 : nullptr;

    cudaFuncSetAttribute(k_gemm, cudaFuncAttributeMaxDynamicSharedMemorySize,
                         SM_TOT);

    k_prep_e<<<(K + 255) / 256, 256>>>(emb, K);      // 1
    k_prep_x<<<(N + 255) / 256, 256>>>(x, N);        // 2
    k_zero<<<1, 1>>>();                              // 3
    k_gemm<<<N / BM, 256, SM_TOT>>>(x, emb, out, outIdx, N, K);  // 4 <- profiled
    if (has_loss) k_fin<<<1, 1>>>(out, N);           // 5
}

// round 15
// speedup vs baseline: 2.3266x; 1.0476x over previous
#include <cuda_runtime.h>
#include <cuda_bf16.h>
#include <cstdint>
#include <cfloat>

// VectorQuantizer: x [N,256] fp32, emb [K,256] fp32.
// Out (fp32): quantized [N*256] | loss [1] | indices [N].
// R15 = R14 gemm core (64x64 tile, 16x32 warp tiles, single-buffer E,
// 3 blocks/SM) with x-prep FUSED into the gemm block (no g_xb, 3 launches).

#define DIM   256
#define NMAX  65536
#define KMAX  4096
#define CAP   128
#define MG    2e-3f
#define BM    64
#define BN    64
#define NCH   (KMAX / BN)

__device__ __align__(16) float  g_c[KMAX];
__device__ unsigned int   g_cnt[NMAX];
__device__ unsigned long long g_cand[(size_t)NMAX * CAP];
__device__ __align__(16) __nv_bfloat16 g_eb[(size_t)KMAX * DIM];
__device__ double         g_acc;

// ---------------------------------------------------------------------------
// prep_e: bf16 convert + exact seq fp32 code norms; zeroes loss accumulator.
// ---------------------------------------------------------------------------
__global__ __launch_bounds__(256) void k_prep_e(const float* __restrict__ emb, int K) {
    int k = blockIdx.x * blockDim.x + threadIdx.x;
    if (k == 0) g_acc = 0.0;
    if (k >= K) return;
    const float4* er = (const float4*)(emb + (size_t)k * DIM);
    __nv_bfloat162* dst = (__nv_bfloat162*)(g_eb + (size_t)k * DIM);
    float s = 0.0f;
    #pragma unroll 8
    for (int i = 0; i < 64; i++) {
        float4 v = __ldg(er + i);
        s = __fadd_rn(s, __fmul_rn(v.x, v.x));
        s = __fadd_rn(s, __fmul_rn(v.y, v.y));
        s = __fadd_rn(s, __fmul_rn(v.z, v.z));
        s = __fadd_rn(s, __fmul_rn(v.w, v.w));
        dst[2 * i + 0] = __floats2bfloat162_rn(v.x, v.y);
        dst[2 * i + 1] = __floats2bfloat162_rn(v.z, v.w);
    }
    g_c[k] = s;
}

// ---------------------------------------------------------------------------
__device__ __forceinline__ void cpa16(uint32_t s, const void* g) {
    asm volatile("cp.async.cg.shared.global [%0], [%1], 16;\n" :: "r"(s), "l"(g));
}
__device__ __forceinline__ void ldsm4(uint32_t* r, uint32_t a) {
    asm volatile("ldmatrix.sync.aligned.m8n8.x4.shared.b16 {%0,%1,%2,%3}, [%4];"
        : "=r"(r[0]), "=r"(r[1]), "=r"(r[2]), "=r"(r[3]) : "r"(a));
}
__device__ __forceinline__ void mma16816(float* d, const uint32_t* a,
                                         uint32_t b0, uint32_t b1) {
    asm volatile("mma.sync.aligned.m16n8k16.row.col.f32.bf16.bf16.f32 "
        "{%0,%1,%2,%3}, {%4,%5,%6,%7}, {%8,%9}, {%0,%1,%2,%3};"
        : "+f"(d[0]), "+f"(d[1]), "+f"(d[2]), "+f"(d[3])
        : "r"(a[0]), "r"(a[1]), "r"(a[2]), "r"(a[3]), "r"(b0), "r"(b1));
}

// bf16 tile: row r = 512B (256 dims), 32 units of 16B, low-3-bit XOR swizzle
__device__ __forceinline__ uint32_t xoff(int r, int j) {
    return (uint32_t)((r << 9) + (((j & 24) | ((j ^ r) & 7)) << 4));
}

// smem map (bytes)
#define SM_XS  0                       // 64*512 = 32768
#define SM_ES  32768                   // 64*512 = 32768 (single buffer)
#define SM_SC  (SM_ES + 32768)         // 2 x 256B c chunks (64 floats each)
#define SM_SS  (SM_SC + 512)           // 64 * 4
#define SM_RM  (SM_SS + 256)           // 64 * 4
#define SM_SI  (SM_RM + 256)           // 64 * 4 (final indices)
#define SM_DR  (SM_SI + 256)           // 8 doubles
#define SM_TOT (SM_DR + 64)

__device__ __forceinline__ unsigned long long exact_pack(
        const float* xr, const float* emb, float Sv, unsigned int k) {
    const float* er = emb + (size_t)k * DIM;
    float m = 0.0f;
    #pragma unroll 4
    for (int i = 0; i < 64; i++) {
        float4 xv = __ldg((const float4*)xr + i);
        float4 ev = __ldg((const float4*)er + i);
        m = __fmaf_rn(xv.x, ev.x, m);
        m = __fmaf_rn(xv.y, ev.y, m);
        m = __fmaf_rn(xv.z, ev.z, m);
        m = __fmaf_rn(xv.w, ev.w, m);
    }
    float d = __fadd_rn(__fmaf_rn(-2.0f, m, Sv), g_c[k]);
    return ((unsigned long long)__float_as_uint(d) << 32) | k;
}

__global__ __launch_bounds__(256, 3) void k_gemm(const float* __restrict__ x,
                                                 const float* __restrict__ emb,
                                                 float* __restrict__ out,
                                                 float* __restrict__ outIdx,
                                                 int N, int K) {
    extern __shared__ char smem[];
    const uint32_t sb = (uint32_t)__cvta_generic_to_shared(smem);
    float*  sS   = (float*)(smem + SM_SS);
    int*    srm  = (int*)  (smem + SM_RM);
    int*    sidx = (int*)  (smem + SM_SI);
    double* sred = (double*)(smem + SM_DR);

    const int tid  = threadIdx.x;
    const int lane = tid & 31, wid = tid >> 5;
    const int rb   = blockIdx.x * BM;

    // issue E chunk 0 + c chunk 0 loads FIRST (fly under x conversion)
    for (int i = tid; i < BN * 32; i += 256) {
        int r = i >> 5, j = i & 31;
        cpa16(sb + SM_ES + xoff(r, j), g_eb + (size_t)r * DIM + j * 8);
    }
    if (tid < 16) cpa16(sb + SM_SC + tid * 16, g_c + tid * 4);
    asm volatile("cp.async.commit_group;\n");

    // fused x-prep: convert this block's 64 fp32 rows into swizzled bf16 smem
    {
        const float4* xr4 = (const float4*)(x + (size_t)rb * DIM);
        for (int u = tid; u < BM * 32; u += 256) {
            int r = u >> 5, j = u & 31;
            float4 v0 = __ldg(xr4 + r * 64 + j * 2);
            float4 v1 = __ldg(xr4 + r * 64 + j * 2 + 1);
            __nv_bfloat162 h0 = __floats2bfloat162_rn(v0.x, v0.y);
            __nv_bfloat162 h1 = __floats2bfloat162_rn(v0.z, v0.w);
            __nv_bfloat162 h2 = __floats2bfloat162_rn(v1.x, v1.y);
            __nv_bfloat162 h3 = __floats2bfloat162_rn(v1.z, v1.w);
            uint4 pk;
            pk.x = *reinterpret_cast<uint32_t*>(&h0);
            pk.y = *reinterpret_cast<uint32_t*>(&h1);
            pk.z = *reinterpret_cast<uint32_t*>(&h2);
            pk.w = *reinterpret_cast<uint32_t*>(&h3);
            *reinterpret_cast<uint4*>(smem + SM_XS + xoff(r, j)) = pk;
        }
    }

    // exact per-row S chains (bit-exact seq fp32) + per-row state init
    if (tid < BM) {
        const float4* xr = (const float4*)(x + (size_t)(rb + tid) * DIM);
        float s = 0.0f;
        #pragma unroll 8
        for (int i = 0; i < 64; i++) {
            float4 v = __ldg(xr + i);
            s = __fadd_rn(s, __fmul_rn(v.x, v.x));
            s = __fadd_rn(s, __fmul_rn(v.y, v.y));
            s = __fadd_rn(s, __fmul_rn(v.z, v.z));
            s = __fadd_rn(s, __fmul_rn(v.w, v.w));
        }
        sS[tid]  = s;
        srm[tid] = 0x7f7fffff;
        g_cnt[rb + tid] = 0u;          // block-private rows: reset each replay
    }

    const int mi = wid >> 1;       // 0..3 : 16-row group
    const int ni = wid & 1;        // 0..1 : 32-col group
    const int g  = lane >> 2, t = lane & 3;

    asm volatile("cp.async.wait_group 0;\n");
    __syncthreads();

    for (int ci = 0; ci < NCH; ci++) {
        float acc[4][4];               // [nn 8-col group][quad]
        #pragma unroll
        for (int nn = 0; nn < 4; nn++)
            #pragma unroll
            for (int q = 0; q < 4; q++) acc[nn][q] = 0.0f;

        #pragma unroll
        for (int ks = 0; ks < 16; ks++) {
            uint32_t a[4], b[2][4];
            {
                int r = mi * 16 + (lane & 7) + ((lane >> 3) & 1) * 8;
                ldsm4(a, sb + SM_XS + xoff(r, ks * 2 + (lane >> 4)));
            }
            #pragma unroll
            for (int nb2 = 0; nb2 < 2; nb2++) {
                int r = ni * 32 + nb2 * 16 + (lane & 7) + (lane >> 4) * 8;
                ldsm4(b[nb2], sb + SM_ES + xoff(r, ks * 2 + ((lane >> 3) & 1)));
            }
            #pragma unroll
            for (int nb2 = 0; nb2 < 2; nb2++) {
                mma16816(acc[nb2 * 2 + 0], a, b[nb2][0], b[nb2][1]);
                mma16816(acc[nb2 * 2 + 1], a, b[nb2][2], b[nb2][3]);
            }
        }

        // all warps done reading the single E buffer
        __syncthreads();

        // issue next chunk's loads; they fly under the epilogue below
        if (ci + 1 < NCH) {
            for (int i = tid; i < BN * 32; i += 256) {
                int r = i >> 5, j = i & 31;
                cpa16(sb + SM_ES + xoff(r, j),
                      g_eb + (size_t)((ci + 1) * BN + r) * DIM + j * 8);
            }
            if (tid < 16) cpa16(sb + SM_SC + ((ci + 1) & 1) * 256 + tid * 16,
                                g_c + (ci + 1) * BN + tid * 4);
            asm volatile("cp.async.commit_group;\n");
        }

        // distances in place: acc <- fadd(fma(-2,acc,S), c)
        const float* scb = (const float*)(smem + SM_SC + (ci & 1) * 256);
        const float Sv  = sS[mi * 16 + g];
        const float Sv2 = sS[mi * 16 + g + 8];
        #pragma unroll
        for (int nn = 0; nn < 4; nn++) {
            const int cl = ni * 32 + ((nn >> 1) << 4) + ((nn & 1) << 3) + 2 * t;
            acc[nn][0] = __fadd_rn(__fmaf_rn(-2.0f, acc[nn][0], Sv),  scb[cl]);
            acc[nn][1] = __fadd_rn(__fmaf_rn(-2.0f, acc[nn][1], Sv),  scb[cl + 1]);
            acc[nn][2] = __fadd_rn(__fmaf_rn(-2.0f, acc[nn][2], Sv2), scb[cl]);
            acc[nn][3] = __fadd_rn(__fmaf_rn(-2.0f, acc[nn][3], Sv2), scb[cl + 1]);
        }

        if (ci == 0) {
            // two-phase for the first chunk (running min not yet seeded)
            #pragma unroll
            for (int h = 0; h < 2; h++) {
                const int rl = mi * 16 + g + h * 8;
                float lmin = FLT_MAX;
                #pragma unroll
                for (int nn = 0; nn < 4; nn++)
                    #pragma unroll
                    for (int q = 0; q < 2; q++)
                        lmin = fminf(lmin, acc[nn][h * 2 + q]);
                lmin = fminf(lmin, __shfl_xor_sync(0xffffffffu, lmin, 1));
                lmin = fminf(lmin, __shfl_xor_sync(0xffffffffu, lmin, 2));
                if (t == 0) atomicMin(&srm[rl], __float_as_int(lmin));
            }
            __syncthreads();
        }
        // appends vs (possibly stale) running min — superset-safe
        const int cbase = ci * BN + ni * 32;
        #pragma unroll
        for (int h = 0; h < 2; h++) {
            const int rl  = mi * 16 + g + h * 8;
            const float rmw = __int_as_float(srm[rl]) + MG;
            float lmin = FLT_MAX;
            #pragma unroll
            for (int nn = 0; nn < 4; nn++)
                #pragma unroll
                for (int q = 0; q < 2; q++) {
                    float dist = acc[nn][h * 2 + q];
                    lmin = fminf(lmin, dist);
                    if (dist <= rmw) {
                        unsigned int pos = atomicAdd(&g_cnt[rb + rl], 1u);
                        if (pos < CAP)
                            g_cand[(size_t)(rb + rl) * CAP + pos] =
                                ((unsigned long long)__float_as_uint(dist) << 32)
                                | (unsigned int)(cbase + ((nn >> 1) << 4)
                                                 + ((nn & 1) << 3) + 2 * t + q);
                    }
                }
            if (ci > 0) {   // chunk 0 already folded its min in phase A
                lmin = fminf(lmin, __shfl_xor_sync(0xffffffffu, lmin, 1));
                lmin = fminf(lmin, __shfl_xor_sync(0xffffffffu, lmin, 2));
                if (t == 0) atomicMin(&srm[rl], __float_as_int(lmin));
            }
        }

        // next chunk's E tile must be resident before the next mma loop
        asm volatile("cp.async.wait_group 0;\n");
        __syncthreads();
    }

    // ---- fused tail 1: exact rescore (one warp per row, 8 rows/warp) ----
    for (int rr = wid; rr < BM; rr += 8) {
        const int n = rb + rr;
        const unsigned int cnt = g_cnt[n];
        const float Sv  = sS[rr];
        const float thr = __int_as_float(srm[rr]) + MG;
        const float* xr = x + (size_t)n * DIM;
        unsigned long long best = 0xffffffffffffffffULL;
        if (cnt <= CAP) {
            for (unsigned int e = lane; e < cnt; e += 32) {
                unsigned long long ent = g_cand[(size_t)n * CAP + e];
                float dt = __uint_as_float((unsigned int)(ent >> 32));
                if (dt > thr) continue;
                unsigned long long v =
                    exact_pack(xr, emb, Sv, (unsigned int)(ent & 0xffffffffu));
                if (v < best) best = v;
            }
        } else {  // overflow fallback: exact full scan
            for (int k = lane; k < K; k += 32) {
                unsigned long long v = exact_pack(xr, emb, Sv, (unsigned int)k);
                if (v < best) best = v;
            }
        }
        #pragma unroll
        for (int o = 16; o; o >>= 1) {
            unsigned long long v = __shfl_xor_sync(0xffffffffu, best, o);
            if (v < best) best = v;
        }
        if (lane == 0) sidx[rr] = (int)(best & 0xffffffffu);
    }
    __syncthreads();

    // ---- fused tail 2: quantized output + loss partial + indices ----
    double ls = 0.0;
    for (int rr = wid; rr < BM; rr += 8) {
        const int n = rb + rr;
        const int idx = sidx[rr];
        if (lane == 0 && outIdx != nullptr) outIdx[n] = (float)idx;
        const float4* xv4 = (const float4*)(x + (size_t)n * DIM);
        const float4* ev4 = (const float4*)(emb + (size_t)idx * DIM);
        float4* ov4 = (float4*)(out + (size_t)n * DIM);
        for (int i = lane; i < 64; i += 32) {
            float4 xv = __ldg(xv4 + i);
            float4 ev = __ldg(ev4 + i);
            float d0 = __fsub_rn(ev.x, xv.x), d1 = __fsub_rn(ev.y, xv.y);
            float d2 = __fsub_rn(ev.z, xv.z), d3 = __fsub_rn(ev.w, xv.w);
            float4 o;
            o.x = __fadd_rn(xv.x, d0); o.y = __fadd_rn(xv.y, d1);
            o.z = __fadd_rn(xv.z, d2); o.w = __fadd_rn(xv.w, d3);
            ov4[i] = o;
            ls += (double)__fmul_rn(d0, d0) + (double)__fmul_rn(d1, d1)
                + (double)__fmul_rn(d2, d2) + (double)__fmul_rn(d3, d3);
        }
    }
    #pragma unroll
    for (int o = 16; o; o >>= 1) ls += __shfl_xor_sync(0xffffffffu, ls, o);
    if (lane == 0) sred[wid] = ls;
    __syncthreads();
    if (tid == 0) {
        double s = 0.0;
        #pragma unroll
        for (int w = 0; w < 8; w++) s += sred[w];
        atomicAdd(&g_acc, s);
    }
}

__global__ void k_fin(float* __restrict__ out, int N) {
    double m = g_acc / ((double)N * (double)DIM);
    float L = (float)m;
    out[(size_t)N * DIM] = __fadd_rn(L, __fmul_rn(0.25f, L));
}

// ---------------------------------------------------------------------------
extern "C" void kernel_launch(void* const* d_in, const int* in_sizes, int n_in,
                              void* d_out, int out_size) {
    const float* x   = (const float*)d_in[0];
    const float* emb = (const float*)d_in[1];
    const int N = in_sizes[0] / DIM;
    const int K = in_sizes[1] / DIM;
    float* out = (float*)d_out;

    const long long Nq = (long long)N * DIM;
    const bool has_loss = (long long)out_size > Nq;
    const bool has_idx  = (long long)out_size >= Nq + 1 + N;
    float* outIdx = has_idx ? out + Nq + 1 : nullptr;

    cudaFuncSetAttribute(k_gemm, cudaFuncAttributeMaxDynamicSharedMemorySize,
                         SM_TOT);

    k_prep_e<<<(K + 255) / 256, 256>>>(emb, K);
    k_gemm<<<N / BM, 256, SM_TOT>>>(x, emb, out, outIdx, N, K);
    if (has_loss) k_fin<<<1, 1>>>(out, N);
}

// round 16
// speedup vs baseline: 2.3688x; 1.0181x over previous
#include <cuda_runtime.h>
#include <cuda_bf16.h>
#include <cstdint>
#include <cfloat>

// VectorQuantizer: x [N,256] fp32, emb [K,256] fp32.
// Out (fp32): quantized [N*256] | loss [1] | indices [N].
// R16 = R15 gemm core + prep_e split (wide convert + spread norm chains)
// + k_fin folded into k_gemm via last-block-done (self-resetting state).

#define DIM   256
#define NMAX  65536
#define KMAX  4096
#define CAP   128
#define MG    2e-3f
#define BM    64
#define BN    64
#define NCH   (KMAX / BN)

__device__ __align__(16) float  g_c[KMAX];
__device__ unsigned int   g_cnt[NMAX];
__device__ unsigned long long g_cand[(size_t)NMAX * CAP];
__device__ __align__(16) __nv_bfloat16 g_eb[(size_t)KMAX * DIM];
__device__ double         g_acc;     // zero-init; self-reset by last block
__device__ unsigned int   g_fin;     // zero-init; self-reset by last block

// ---------------------------------------------------------------------------
// wide bf16 convert of emb (memory-bound, full-chip)
// ---------------------------------------------------------------------------
__global__ __launch_bounds__(256) void k_cvt_e(const float* __restrict__ emb, int n4) {
    int i = blockIdx.x * blockDim.x + threadIdx.x;
    if (i >= n4) return;
    float4 v = ((const float4*)emb)[i];
    __nv_bfloat162* d2 = (__nv_bfloat162*)g_eb;
    d2[2 * i + 0] = __floats2bfloat162_rn(v.x, v.y);
    d2[2 * i + 1] = __floats2bfloat162_rn(v.z, v.w);
}

// exact seq fp32 code norms; 32-thread blocks spread chains across SMs
__global__ __launch_bounds__(32) void k_norm_e(const float* __restrict__ emb, int K) {
    int k = blockIdx.x * blockDim.x + threadIdx.x;
    if (k >= K) return;
    const float4* er = (const float4*)(emb + (size_t)k * DIM);
    float s = 0.0f;
    #pragma unroll 8
    for (int i = 0; i < 64; i++) {
        float4 v = __ldg(er + i);
        s = __fadd_rn(s, __fmul_rn(v.x, v.x));
        s = __fadd_rn(s, __fmul_rn(v.y, v.y));
        s = __fadd_rn(s, __fmul_rn(v.z, v.z));
        s = __fadd_rn(s, __fmul_rn(v.w, v.w));
    }
    g_c[k] = s;
}

// ---------------------------------------------------------------------------
__device__ __forceinline__ void cpa16(uint32_t s, const void* g) {
    asm volatile("cp.async.cg.shared.global [%0], [%1], 16;\n" :: "r"(s), "l"(g));
}
__device__ __forceinline__ void ldsm4(uint32_t* r, uint32_t a) {
    asm volatile("ldmatrix.sync.aligned.m8n8.x4.shared.b16 {%0,%1,%2,%3}, [%4];"
        : "=r"(r[0]), "=r"(r[1]), "=r"(r[2]), "=r"(r[3]) : "r"(a));
}
__device__ __forceinline__ void mma16816(float* d, const uint32_t* a,
                                         uint32_t b0, uint32_t b1) {
    asm volatile("mma.sync.aligned.m16n8k16.row.col.f32.bf16.bf16.f32 "
        "{%0,%1,%2,%3}, {%4,%5,%6,%7}, {%8,%9}, {%0,%1,%2,%3};"
        : "+f"(d[0]), "+f"(d[1]), "+f"(d[2]), "+f"(d[3])
        : "r"(a[0]), "r"(a[1]), "r"(a[2]), "r"(a[3]), "r"(b0), "r"(b1));
}

// bf16 tile: row r = 512B (256 dims), 32 units of 16B, low-3-bit XOR swizzle
__device__ __forceinline__ uint32_t xoff(int r, int j) {
    return (uint32_t)((r << 9) + (((j & 24) | ((j ^ r) & 7)) << 4));
}

// smem map (bytes)
#define SM_XS  0                       // 64*512 = 32768
#define SM_ES  32768                   // 64*512 = 32768 (single buffer)
#define SM_SC  (SM_ES + 32768)         // 2 x 256B c chunks (64 floats each)
#define SM_SS  (SM_SC + 512)           // 64 * 4
#define SM_RM  (SM_SS + 256)           // 64 * 4
#define SM_SI  (SM_RM + 256)           // 64 * 4 (final indices)
#define SM_DR  (SM_SI + 256)           // 8 doubles
#define SM_TOT (SM_DR + 64)

__device__ __forceinline__ unsigned long long exact_pack(
        const float* xr, const float* emb, float Sv, unsigned int k) {
    const float* er = emb + (size_t)k * DIM;
    float m = 0.0f;
    #pragma unroll 4
    for (int i = 0; i < 64; i++) {
        float4 xv = __ldg((const float4*)xr + i);
        float4 ev = __ldg((const float4*)er + i);
        m = __fmaf_rn(xv.x, ev.x, m);
        m = __fmaf_rn(xv.y, ev.y, m);
        m = __fmaf_rn(xv.z, ev.z, m);
        m = __fmaf_rn(xv.w, ev.w, m);
    }
    float d = __fadd_rn(__fmaf_rn(-2.0f, m, Sv), g_c[k]);
    return ((unsigned long long)__float_as_uint(d) << 32) | k;
}

__global__ __launch_bounds__(256, 3) void k_gemm(const float* __restrict__ x,
                                                 const float* __restrict__ emb,
                                                 float* __restrict__ out,
                                                 float* __restrict__ outIdx,
                                                 int N, int K, int hasLoss) {
    extern __shared__ char smem[];
    const uint32_t sb = (uint32_t)__cvta_generic_to_shared(smem);
    float*  sS   = (float*)(smem + SM_SS);
    int*    srm  = (int*)  (smem + SM_RM);
    int*    sidx = (int*)  (smem + SM_SI);
    double* sred = (double*)(smem + SM_DR);

    const int tid  = threadIdx.x;
    const int lane = tid & 31, wid = tid >> 5;
    const int rb   = blockIdx.x * BM;

    // issue E chunk 0 + c chunk 0 loads FIRST (fly under x conversion)
    for (int i = tid; i < BN * 32; i += 256) {
        int r = i >> 5, j = i & 31;
        cpa16(sb + SM_ES + xoff(r, j), g_eb + (size_t)r * DIM + j * 8);
    }
    if (tid < 16) cpa16(sb + SM_SC + tid * 16, g_c + tid * 4);
    asm volatile("cp.async.commit_group;\n");

    // fused x-prep: convert this block's 64 fp32 rows into swizzled bf16 smem
    {
        const float4* xr4 = (const float4*)(x + (size_t)rb * DIM);
        for (int u = tid; u < BM * 32; u += 256) {
            int r = u >> 5, j = u & 31;
            float4 v0 = __ldg(xr4 + r * 64 + j * 2);
            float4 v1 = __ldg(xr4 + r * 64 + j * 2 + 1);
            __nv_bfloat162 h0 = __floats2bfloat162_rn(v0.x, v0.y);
            __nv_bfloat162 h1 = __floats2bfloat162_rn(v0.z, v0.w);
            __nv_bfloat162 h2 = __floats2bfloat162_rn(v1.x, v1.y);
            __nv_bfloat162 h3 = __floats2bfloat162_rn(v1.z, v1.w);
            uint4 pk;
            pk.x = *reinterpret_cast<uint32_t*>(&h0);
            pk.y = *reinterpret_cast<uint32_t*>(&h1);
            pk.z = *reinterpret_cast<uint32_t*>(&h2);
            pk.w = *reinterpret_cast<uint32_t*>(&h3);
            *reinterpret_cast<uint4*>(smem + SM_XS + xoff(r, j)) = pk;
        }
    }

    // exact per-row S chains (bit-exact seq fp32) + per-row state init
    if (tid < BM) {
        const float4* xr = (const float4*)(x + (size_t)(rb + tid) * DIM);
        float s = 0.0f;
        #pragma unroll 8
        for (int i = 0; i < 64; i++) {
            float4 v = __ldg(xr + i);
            s = __fadd_rn(s, __fmul_rn(v.x, v.x));
            s = __fadd_rn(s, __fmul_rn(v.y, v.y));
            s = __fadd_rn(s, __fmul_rn(v.z, v.z));
            s = __fadd_rn(s, __fmul_rn(v.w, v.w));
        }
        sS[tid]  = s;
        srm[tid] = 0x7f7fffff;
        g_cnt[rb + tid] = 0u;          // block-private rows: reset each replay
    }

    const int mi = wid >> 1;       // 0..3 : 16-row group
    const int ni = wid & 1;        // 0..1 : 32-col group
    const int g  = lane >> 2, t = lane & 3;

    asm volatile("cp.async.wait_group 0;\n");
    __syncthreads();

    for (int ci = 0; ci < NCH; ci++) {
        float acc[4][4];               // [nn 8-col group][quad]
        #pragma unroll
        for (int nn = 0; nn < 4; nn++)
            #pragma unroll
            for (int q = 0; q < 4; q++) acc[nn][q] = 0.0f;

        #pragma unroll
        for (int ks = 0; ks < 16; ks++) {
            uint32_t a[4], b[2][4];
            {
                int r = mi * 16 + (lane & 7) + ((lane >> 3) & 1) * 8;
                ldsm4(a, sb + SM_XS + xoff(r, ks * 2 + (lane >> 4)));
            }
            #pragma unroll
            for (int nb2 = 0; nb2 < 2; nb2++) {
                int r = ni * 32 + nb2 * 16 + (lane & 7) + (lane >> 4) * 8;
                ldsm4(b[nb2], sb + SM_ES + xoff(r, ks * 2 + ((lane >> 3) & 1)));
            }
            #pragma unroll
            for (int nb2 = 0; nb2 < 2; nb2++) {
                mma16816(acc[nb2 * 2 + 0], a, b[nb2][0], b[nb2][1]);
                mma16816(acc[nb2 * 2 + 1], a, b[nb2][2], b[nb2][3]);
            }
        }

        // all warps done reading the single E buffer
        __syncthreads();

        // issue next chunk's loads; they fly under the epilogue below
        if (ci + 1 < NCH) {
            for (int i = tid; i < BN * 32; i += 256) {
                int r = i >> 5, j = i & 31;
                cpa16(sb + SM_ES + xoff(r, j),
                      g_eb + (size_t)((ci + 1) * BN + r) * DIM + j * 8);
            }
            if (tid < 16) cpa16(sb + SM_SC + ((ci + 1) & 1) * 256 + tid * 16,
                                g_c + (ci + 1) * BN + tid * 4);
            asm volatile("cp.async.commit_group;\n");
        }

        // distances in place: acc <- fadd(fma(-2,acc,S), c)
        const float* scb = (const float*)(smem + SM_SC + (ci & 1) * 256);
        const float Sv  = sS[mi * 16 + g];
        const float Sv2 = sS[mi * 16 + g + 8];
        #pragma unroll
        for (int nn = 0; nn < 4; nn++) {
            const int cl = ni * 32 + ((nn >> 1) << 4) + ((nn & 1) << 3) + 2 * t;
            acc[nn][0] = __fadd_rn(__fmaf_rn(-2.0f, acc[nn][0], Sv),  scb[cl]);
            acc[nn][1] = __fadd_rn(__fmaf_rn(-2.0f, acc[nn][1], Sv),  scb[cl + 1]);
            acc[nn][2] = __fadd_rn(__fmaf_rn(-2.0f, acc[nn][2], Sv2), scb[cl]);
            acc[nn][3] = __fadd_rn(__fmaf_rn(-2.0f, acc[nn][3], Sv2), scb[cl + 1]);
        }

        if (ci == 0) {
            // two-phase for the first chunk (running min not yet seeded)
            #pragma unroll
            for (int h = 0; h < 2; h++) {
                const int rl = mi * 16 + g + h * 8;
                float lmin = FLT_MAX;
                #pragma unroll
                for (int nn = 0; nn < 4; nn++)
                    #pragma unroll
                    for (int q = 0; q < 2; q++)
                        lmin = fminf(lmin, acc[nn][h * 2 + q]);
                lmin = fminf(lmin, __shfl_xor_sync(0xffffffffu, lmin, 1));
                lmin = fminf(lmin, __shfl_xor_sync(0xffffffffu, lmin, 2));
                if (t == 0) atomicMin(&srm[rl], __float_as_int(lmin));
            }
            __syncthreads();
        }
        // appends vs (possibly stale) running min — superset-safe
        const int cbase = ci * BN + ni * 32;
        #pragma unroll
        for (int h = 0; h < 2; h++) {
            const int rl  = mi * 16 + g + h * 8;
            const float rmw = __int_as_float(srm[rl]) + MG;
            float lmin = FLT_MAX;
            #pragma unroll
            for (int nn = 0; nn < 4; nn++)
                #pragma unroll
                for (int q = 0; q < 2; q++) {
                    float dist = acc[nn][h * 2 + q];
                    lmin = fminf(lmin, dist);
                    if (dist <= rmw) {
                        unsigned int pos = atomicAdd(&g_cnt[rb + rl], 1u);
                        if (pos < CAP)
                            g_cand[(size_t)(rb + rl) * CAP + pos] =
                                ((unsigned long long)__float_as_uint(dist) << 32)
                                | (unsigned int)(cbase + ((nn >> 1) << 4)
                                                 + ((nn & 1) << 3) + 2 * t + q);
                    }
                }
            if (ci > 0) {   // chunk 0 already folded its min in phase A
                lmin = fminf(lmin, __shfl_xor_sync(0xffffffffu, lmin, 1));
                lmin = fminf(lmin, __shfl_xor_sync(0xffffffffu, lmin, 2));
                if (t == 0) atomicMin(&srm[rl], __float_as_int(lmin));
            }
        }

        // next chunk's E tile must be resident before the next mma loop
        asm volatile("cp.async.wait_group 0;\n");
        __syncthreads();
    }

    // ---- fused tail 1: exact rescore (one warp per row, 8 rows/warp) ----
    for (int rr = wid; rr < BM; rr += 8) {
        const int n = rb + rr;
        const unsigned int cnt = g_cnt[n];
        const float Sv  = sS[rr];
        const float thr = __int_as_float(srm[rr]) + MG;
        const float* xr = x + (size_t)n * DIM;
        unsigned long long best = 0xffffffffffffffffULL;
        if (cnt <= CAP) {
            for (unsigned int e = lane; e < cnt; e += 32) {
                unsigned long long ent = g_cand[(size_t)n * CAP + e];
                float dt = __uint_as_float((unsigned int)(ent >> 32));
                if (dt > thr) continue;
                unsigned long long v =
                    exact_pack(xr, emb, Sv, (unsigned int)(ent & 0xffffffffu));
                if (v < best) best = v;
            }
        } else {  // overflow fallback: exact full scan
            for (int k = lane; k < K; k += 32) {
                unsigned long long v = exact_pack(xr, emb, Sv, (unsigned int)k);
                if (v < best) best = v;
            }
        }
        #pragma unroll
        for (int o = 16; o; o >>= 1) {
            unsigned long long v = __shfl_xor_sync(0xffffffffu, best, o);
            if (v < best) best = v;
        }
        if (lane == 0) sidx[rr] = (int)(best & 0xffffffffu);
    }
    __syncthreads();

    // ---- fused tail 2: quantized output + loss partial + indices ----
    double ls = 0.0;
    for (int rr = wid; rr < BM; rr += 8) {
        const int n = rb + rr;
        const int idx = sidx[rr];
        if (lane == 0 && outIdx != nullptr) outIdx[n] = (float)idx;
        const float4* xv4 = (const float4*)(x + (size_t)n * DIM);
        const float4* ev4 = (const float4*)(emb + (size_t)idx * DIM);
        float4* ov4 = (float4*)(out + (size_t)n * DIM);
        for (int i = lane; i < 64; i += 32) {
            float4 xv = __ldg(xv4 + i);
            float4 ev = __ldg(ev4 + i);
            float d0 = __fsub_rn(ev.x, xv.x), d1 = __fsub_rn(ev.y, xv.y);
            float d2 = __fsub_rn(ev.z, xv.z), d3 = __fsub_rn(ev.w, xv.w);
            float4 o;
            o.x = __fadd_rn(xv.x, d0); o.y = __fadd_rn(xv.y, d1);
            o.z = __fadd_rn(xv.z, d2); o.w = __fadd_rn(xv.w, d3);
            ov4[i] = o;
            ls += (double)__fmul_rn(d0, d0) + (double)__fmul_rn(d1, d1)
                + (double)__fmul_rn(d2, d2) + (double)__fmul_rn(d3, d3);
        }
    }
    #pragma unroll
    for (int o = 16; o; o >>= 1) ls += __shfl_xor_sync(0xffffffffu, ls, o);
    if (lane == 0) sred[wid] = ls;
    __syncthreads();

    // ---- folded k_fin: last finishing block computes loss + resets state ----
    if (tid == 0) {
        double s = 0.0;
        #pragma unroll
        for (int w = 0; w < 8; w++) s += sred[w];
        atomicAdd(&g_acc, s);
        __threadfence();
        unsigned int old = atomicAdd(&g_fin, 1u);
        if (old == gridDim.x - 1) {
            double m = g_acc / ((double)N * (double)DIM);
            float L = (float)m;
            if (hasLoss) out[(size_t)N * DIM] = __fadd_rn(L, __fmul_rn(0.25f, L));
            g_acc = 0.0;         // self-reset for next graph replay
            g_fin = 0u;
            __threadfence();
        }
    }
}

// ---------------------------------------------------------------------------
extern "C" void kernel_launch(void* const* d_in, const int* in_sizes, int n_in,
                              void* d_out, int out_size) {
    const float* x   = (const float*)d_in[0];
    const float* emb = (const float*)d_in[1];
    const int N = in_sizes[0] / DIM;
    const int K = in_sizes[1] / DIM;
    float* out = (float*)d_out;

    const long long Nq = (long long)N * DIM;
    const int  hasLoss = (long long)out_size > Nq ? 1 : 0;
    const bool has_idx = (long long)out_size >= Nq + 1 + N;
    float* outIdx = has_idx ? out + Nq + 1 : nullptr;

    cudaFuncSetAttribute(k_gemm, cudaFuncAttributeMaxDynamicSharedMemorySize,
                         SM_TOT);

    k_cvt_e<<<(K * DIM / 4 + 255) / 256, 256>>>(emb, K * DIM / 4);
    k_norm_e<<<(K + 31) / 32, 32>>>(emb, K);
    k_gemm<<<N / BM, 256, SM_TOT>>>(x, emb, out, outIdx, N, K, hasLoss);
}

// round 17
// speedup vs baseline: 2.3906x; 1.0092x over previous
#include <cuda_runtime.h>
#include <cuda_bf16.h>
#include <cstdint>
#include <cfloat>

// VectorQuantizer: x [N,256] fp32, emb [K,256] fp32.
// Out (fp32): quantized [N*256] | loss [1] | indices [N].
// R17 = R16 gemm core (unchanged, at legacy-HMMA rate floor) with emb prep
// consolidated into ONE kernel (norm chain + bf16 convert from same loads).

#define DIM   256
#define NMAX  65536
#define KMAX  4096
#define CAP   128
#define MG    2e-3f
#define BM    64
#define BN    64
#define NCH   (KMAX / BN)

__device__ __align__(16) float  g_c[KMAX];
__device__ unsigned int   g_cnt[NMAX];
__device__ unsigned long long g_cand[(size_t)NMAX * CAP];
__device__ __align__(16) __nv_bfloat16 g_eb[(size_t)KMAX * DIM];
__device__ double         g_acc;     // zero-init; self-reset by last block
__device__ unsigned int   g_fin;     // zero-init; self-reset by last block

// ---------------------------------------------------------------------------
// fused emb prep: exact seq fp32 norm chain + bf16 convert, one pass.
// 32-thread blocks spread the 4096 serial chains across all SMs.
// ---------------------------------------------------------------------------
__global__ __launch_bounds__(32) void k_prep_e(const float* __restrict__ emb, int K) {
    int k = blockIdx.x * blockDim.x + threadIdx.x;
    if (k >= K) return;
    const float4* er = (const float4*)(emb + (size_t)k * DIM);
    __nv_bfloat162* dst = (__nv_bfloat162*)(g_eb + (size_t)k * DIM);
    float s = 0.0f;
    #pragma unroll 8
    for (int i = 0; i < 64; i++) {
        float4 v = __ldg(er + i);
        s = __fadd_rn(s, __fmul_rn(v.x, v.x));
        s = __fadd_rn(s, __fmul_rn(v.y, v.y));
        s = __fadd_rn(s, __fmul_rn(v.z, v.z));
        s = __fadd_rn(s, __fmul_rn(v.w, v.w));
        dst[2 * i + 0] = __floats2bfloat162_rn(v.x, v.y);
        dst[2 * i + 1] = __floats2bfloat162_rn(v.z, v.w);
    }
    g_c[k] = s;
}

// ---------------------------------------------------------------------------
__device__ __forceinline__ void cpa16(uint32_t s, const void* g) {
    asm volatile("cp.async.cg.shared.global [%0], [%1], 16;\n" :: "r"(s), "l"(g));
}
__device__ __forceinline__ void ldsm4(uint32_t* r, uint32_t a) {
    asm volatile("ldmatrix.sync.aligned.m8n8.x4.shared.b16 {%0,%1,%2,%3}, [%4];"
        : "=r"(r[0]), "=r"(r[1]), "=r"(r[2]), "=r"(r[3]) : "r"(a));
}
__device__ __forceinline__ void mma16816(float* d, const uint32_t* a,
                                         uint32_t b0, uint32_t b1) {
    asm volatile("mma.sync.aligned.m16n8k16.row.col.f32.bf16.bf16.f32 "
        "{%0,%1,%2,%3}, {%4,%5,%6,%7}, {%8,%9}, {%0,%1,%2,%3};"
        : "+f"(d[0]), "+f"(d[1]), "+f"(d[2]), "+f"(d[3])
        : "r"(a[0]), "r"(a[1]), "r"(a[2]), "r"(a[3]), "r"(b0), "r"(b1));
}

// bf16 tile: row r = 512B (256 dims), 32 units of 16B, low-3-bit XOR swizzle
__device__ __forceinline__ uint32_t xoff(int r, int j) {
    return (uint32_t)((r << 9) + (((j & 24) | ((j ^ r) & 7)) << 4));
}

// smem map (bytes)
#define SM_XS  0                       // 64*512 = 32768
#define SM_ES  32768                   // 64*512 = 32768 (single buffer)
#define SM_SC  (SM_ES + 32768)         // 2 x 256B c chunks (64 floats each)
#define SM_SS  (SM_SC + 512)           // 64 * 4
#define SM_RM  (SM_SS + 256)           // 64 * 4
#define SM_SI  (SM_RM + 256)           // 64 * 4 (final indices)
#define SM_DR  (SM_SI + 256)           // 8 doubles
#define SM_TOT (SM_DR + 64)

__device__ __forceinline__ unsigned long long exact_pack(
        const float* xr, const float* emb, float Sv, unsigned int k) {
    const float* er = emb + (size_t)k * DIM;
    float m = 0.0f;
    #pragma unroll 4
    for (int i = 0; i < 64; i++) {
        float4 xv = __ldg((const float4*)xr + i);
        float4 ev = __ldg((const float4*)er + i);
        m = __fmaf_rn(xv.x, ev.x, m);
        m = __fmaf_rn(xv.y, ev.y, m);
        m = __fmaf_rn(xv.z, ev.z, m);
        m = __fmaf_rn(xv.w, ev.w, m);
    }
    float d = __fadd_rn(__fmaf_rn(-2.0f, m, Sv), g_c[k]);
    return ((unsigned long long)__float_as_uint(d) << 32) | k;
}

__global__ __launch_bounds__(256, 3) void k_gemm(const float* __restrict__ x,
                                                 const float* __restrict__ emb,
                                                 float* __restrict__ out,
                                                 float* __restrict__ outIdx,
                                                 int N, int K, int hasLoss) {
    extern __shared__ char smem[];
    const uint32_t sb = (uint32_t)__cvta_generic_to_shared(smem);
    float*  sS   = (float*)(smem + SM_SS);
    int*    srm  = (int*)  (smem + SM_RM);
    int*    sidx = (int*)  (smem + SM_SI);
    double* sred = (double*)(smem + SM_DR);

    const int tid  = threadIdx.x;
    const int lane = tid & 31, wid = tid >> 5;
    const int rb   = blockIdx.x * BM;

    // issue E chunk 0 + c chunk 0 loads FIRST (fly under x conversion)
    for (int i = tid; i < BN * 32; i += 256) {
        int r = i >> 5, j = i & 31;
        cpa16(sb + SM_ES + xoff(r, j), g_eb + (size_t)r * DIM + j * 8);
    }
    if (tid < 16) cpa16(sb + SM_SC + tid * 16, g_c + tid * 4);
    asm volatile("cp.async.commit_group;\n");

    // fused x-prep: convert this block's 64 fp32 rows into swizzled bf16 smem
    {
        const float4* xr4 = (const float4*)(x + (size_t)rb * DIM);
        for (int u = tid; u < BM * 32; u += 256) {
            int r = u >> 5, j = u & 31;
            float4 v0 = __ldg(xr4 + r * 64 + j * 2);
            float4 v1 = __ldg(xr4 + r * 64 + j * 2 + 1);
            __nv_bfloat162 h0 = __floats2bfloat162_rn(v0.x, v0.y);
            __nv_bfloat162 h1 = __floats2bfloat162_rn(v0.z, v0.w);
            __nv_bfloat162 h2 = __floats2bfloat162_rn(v1.x, v1.y);
            __nv_bfloat162 h3 = __floats2bfloat162_rn(v1.z, v1.w);
            uint4 pk;
            pk.x = *reinterpret_cast<uint32_t*>(&h0);
            pk.y = *reinterpret_cast<uint32_t*>(&h1);
            pk.z = *reinterpret_cast<uint32_t*>(&h2);
            pk.w = *reinterpret_cast<uint32_t*>(&h3);
            *reinterpret_cast<uint4*>(smem + SM_XS + xoff(r, j)) = pk;
        }
    }

    // exact per-row S chains (bit-exact seq fp32) + per-row state init
    if (tid < BM) {
        const float4* xr = (const float4*)(x + (size_t)(rb + tid) * DIM);
        float s = 0.0f;
        #pragma unroll 8
        for (int i = 0; i < 64; i++) {
            float4 v = __ldg(xr + i);
            s = __fadd_rn(s, __fmul_rn(v.x, v.x));
            s = __fadd_rn(s, __fmul_rn(v.y, v.y));
            s = __fadd_rn(s, __fmul_rn(v.z, v.z));
            s = __fadd_rn(s, __fmul_rn(v.w, v.w));
        }
        sS[tid]  = s;
        srm[tid] = 0x7f7fffff;
        g_cnt[rb + tid] = 0u;          // block-private rows: reset each replay
    }

    const int mi = wid >> 1;       // 0..3 : 16-row group
    const int ni = wid & 1;        // 0..1 : 32-col group
    const int g  = lane >> 2, t = lane & 3;

    asm volatile("cp.async.wait_group 0;\n");
    __syncthreads();

    for (int ci = 0; ci < NCH; ci++) {
        float acc[4][4];               // [nn 8-col group][quad]
        #pragma unroll
        for (int nn = 0; nn < 4; nn++)
            #pragma unroll
            for (int q = 0; q < 4; q++) acc[nn][q] = 0.0f;

        #pragma unroll
        for (int ks = 0; ks < 16; ks++) {
            uint32_t a[4], b[2][4];
            {
                int r = mi * 16 + (lane & 7) + ((lane >> 3) & 1) * 8;
                ldsm4(a, sb + SM_XS + xoff(r, ks * 2 + (lane >> 4)));
            }
            #pragma unroll
            for (int nb2 = 0; nb2 < 2; nb2++) {
                int r = ni * 32 + nb2 * 16 + (lane & 7) + (lane >> 4) * 8;
                ldsm4(b[nb2], sb + SM_ES + xoff(r, ks * 2 + ((lane >> 3) & 1)));
            }
            #pragma unroll
            for (int nb2 = 0; nb2 < 2; nb2++) {
                mma16816(acc[nb2 * 2 + 0], a, b[nb2][0], b[nb2][1]);
                mma16816(acc[nb2 * 2 + 1], a, b[nb2][2], b[nb2][3]);
            }
        }

        // all warps done reading the single E buffer
        __syncthreads();

        // issue next chunk's loads; they fly under the epilogue below
        if (ci + 1 < NCH) {
            for (int i = tid; i < BN * 32; i += 256) {
                int r = i >> 5, j = i & 31;
                cpa16(sb + SM_ES + xoff(r, j),
                      g_eb + (size_t)((ci + 1) * BN + r) * DIM + j * 8);
            }
            if (tid < 16) cpa16(sb + SM_SC + ((ci + 1) & 1) * 256 + tid * 16,
                                g_c + (ci + 1) * BN + tid * 4);
            asm volatile("cp.async.commit_group;\n");
        }

        // distances in place: acc <- fadd(fma(-2,acc,S), c)
        const float* scb = (const float*)(smem + SM_SC + (ci & 1) * 256);
        const float Sv  = sS[mi * 16 + g];
        const float Sv2 = sS[mi * 16 + g + 8];
        #pragma unroll
        for (int nn = 0; nn < 4; nn++) {
            const int cl = ni * 32 + ((nn >> 1) << 4) + ((nn & 1) << 3) + 2 * t;
            acc[nn][0] = __fadd_rn(__fmaf_rn(-2.0f, acc[nn][0], Sv),  scb[cl]);
            acc[nn][1] = __fadd_rn(__fmaf_rn(-2.0f, acc[nn][1], Sv),  scb[cl + 1]);
            acc[nn][2] = __fadd_rn(__fmaf_rn(-2.0f, acc[nn][2], Sv2), scb[cl]);
            acc[nn][3] = __fadd_rn(__fmaf_rn(-2.0f, acc[nn][3], Sv2), scb[cl + 1]);
        }

        if (ci == 0) {
            // two-phase for the first chunk (running min not yet seeded)
            #pragma unroll
            for (int h = 0; h < 2; h++) {
                const int rl = mi * 16 + g + h * 8;
                float lmin = FLT_MAX;
                #pragma unroll
                for (int nn = 0; nn < 4; nn++)
                    #pragma unroll
                    for (int q = 0; q < 2; q++)
                        lmin = fminf(lmin, acc[nn][h * 2 + q]);
                lmin = fminf(lmin, __shfl_xor_sync(0xffffffffu, lmin, 1));
                lmin = fminf(lmin, __shfl_xor_sync(0xffffffffu, lmin, 2));
                if (t == 0) atomicMin(&srm[rl], __float_as_int(lmin));
            }
            __syncthreads();
        }
        // appends vs (possibly stale) running min — superset-safe
        const int cbase = ci * BN + ni * 32;
        #pragma unroll
        for (int h = 0; h < 2; h++) {
            const int rl  = mi * 16 + g + h * 8;
            const float rmw = __int_as_float(srm[rl]) + MG;
            float lmin = FLT_MAX;
            #pragma unroll
            for (int nn = 0; nn < 4; nn++)
                #pragma unroll
                for (int q = 0; q < 2; q++) {
                    float dist = acc[nn][h * 2 + q];
                    lmin = fminf(lmin, dist);
                    if (dist <= rmw) {
                        unsigned int pos = atomicAdd(&g_cnt[rb + rl], 1u);
                        if (pos < CAP)
                            g_cand[(size_t)(rb + rl) * CAP + pos] =
                                ((unsigned long long)__float_as_uint(dist) << 32)
                                | (unsigned int)(cbase + ((nn >> 1) << 4)
                                                 + ((nn & 1) << 3) + 2 * t + q);
                    }
                }
            if (ci > 0) {   // chunk 0 already folded its min in phase A
                lmin = fminf(lmin, __shfl_xor_sync(0xffffffffu, lmin, 1));
                lmin = fminf(lmin, __shfl_xor_sync(0xffffffffu, lmin, 2));
                if (t == 0) atomicMin(&srm[rl], __float_as_int(lmin));
            }
        }

        // next chunk's E tile must be resident before the next mma loop
        asm volatile("cp.async.wait_group 0;\n");
        __syncthreads();
    }

    // ---- fused tail 1: exact rescore (one warp per row, 8 rows/warp) ----
    for (int rr = wid; rr < BM; rr += 8) {
        const int n = rb + rr;
        const unsigned int cnt = g_cnt[n];
        const float Sv  = sS[rr];
        const float thr = __int_as_float(srm[rr]) + MG;
        const float* xr = x + (size_t)n * DIM;
        unsigned long long best = 0xffffffffffffffffULL;
        if (cnt <= CAP) {
            for (unsigned int e = lane; e < cnt; e += 32) {
                unsigned long long ent = g_cand[(size_t)n * CAP + e];
                float dt = __uint_as_float((unsigned int)(ent >> 32));
                if (dt > thr) continue;
                unsigned long long v =
                    exact_pack(xr, emb, Sv, (unsigned int)(ent & 0xffffffffu));
                if (v < best) best = v;
            }
        } else {  // overflow fallback: exact full scan
            for (int k = lane; k < K; k += 32) {
                unsigned long long v = exact_pack(xr, emb, Sv, (unsigned int)k);
                if (v < best) best = v;
            }
        }
        #pragma unroll
        for (int o = 16; o; o >>= 1) {
            unsigned long long v = __shfl_xor_sync(0xffffffffu, best, o);
            if (v < best) best = v;
        }
        if (lane == 0) sidx[rr] = (int)(best & 0xffffffffu);
    }
    __syncthreads();

    // ---- fused tail 2: quantized output + loss partial + indices ----
    double ls = 0.0;
    for (int rr = wid; rr < BM; rr += 8) {
        const int n = rb + rr;
        const int idx = sidx[rr];
        if (lane == 0 && outIdx != nullptr) outIdx[n] = (float)idx;
        const float4* xv4 = (const float4*)(x + (size_t)n * DIM);
        const float4* ev4 = (const float4*)(emb + (size_t)idx * DIM);
        float4* ov4 = (float4*)(out + (size_t)n * DIM);
        for (int i = lane; i < 64; i += 32) {
            float4 xv = __ldg(xv4 + i);
            float4 ev = __ldg(ev4 + i);
            float d0 = __fsub_rn(ev.x, xv.x), d1 = __fsub_rn(ev.y, xv.y);
            float d2 = __fsub_rn(ev.z, xv.z), d3 = __fsub_rn(ev.w, xv.w);
            float4 o;
            o.x = __fadd_rn(xv.x, d0); o.y = __fadd_rn(xv.y, d1);
            o.z = __fadd_rn(xv.z, d2); o.w = __fadd_rn(xv.w, d3);
            ov4[i] = o;
            ls += (double)__fmul_rn(d0, d0) + (double)__fmul_rn(d1, d1)
                + (double)__fmul_rn(d2, d2) + (double)__fmul_rn(d3, d3);
        }
    }
    #pragma unroll
    for (int o = 16; o; o >>= 1) ls += __shfl_xor_sync(0xffffffffu, ls, o);
    if (lane == 0) sred[wid] = ls;
    __syncthreads();

    // ---- folded k_fin: last finishing block computes loss + resets state ----
    if (tid == 0) {
        double s = 0.0;
        #pragma unroll
        for (int w = 0; w < 8; w++) s += sred[w];
        atomicAdd(&g_acc, s);
        __threadfence();
        unsigned int old = atomicAdd(&g_fin, 1u);
        if (old == gridDim.x - 1) {
            double m = g_acc / ((double)N * (double)DIM);
            float L = (float)m;
            if (hasLoss) out[(size_t)N * DIM] = __fadd_rn(L, __fmul_rn(0.25f, L));
            g_acc = 0.0;         // self-reset for next graph replay
            g_fin = 0u;
            __threadfence();
        }
    }
}

// ---------------------------------------------------------------------------
extern "C" void kernel_launch(void* const* d_in, const int* in_sizes, int n_in,
                              void* d_out, int out_size) {
    const float* x   = (const float*)d_in[0];
    const float* emb = (const float*)d_in[1];
    const int N = in_sizes[0] / DIM;
    const int K = in_sizes[1] / DIM;
    float* out = (float*)d_out;

    const long long Nq = (long long)N * DIM;
    const int  hasLoss = (long long)out_size > Nq ? 1 : 0;
    const bool has_idx = (long long)out_size >= Nq + 1 + N;
    float* outIdx = has_idx ? out + Nq + 1 : nullptr;

    cudaFuncSetAttribute(k_gemm, cudaFuncAttributeMaxDynamicSharedMemorySize,
                         SM_TOT);

    k_prep_e<<<(K + 31) / 32, 32>>>(emb, K);
    k_gemm<<<N / BM, 256, SM_TOT>>>(x, emb, out, outIdx, N, K, hasLoss);
}